// round 1
// baseline (speedup 1.0000x reference)
#include <cuda_runtime.h>
#include <math.h>

#define S_LEN 2048
#define H_DIM 1024
#define NH 16
#define HD 64
#define H3 3072
#define NE 8
#define TOPK 2
#define FF 2048
#define NSLOT (S_LEN * TOPK)

// ---------------- scratch (static device globals; no allocation) ----------------
__device__ float g_hn[S_LEN * H_DIM];
__device__ float g_qkv[S_LEN * H3];
__device__ float g_attn[S_LEN * H_DIM];
__device__ float g_x1[S_LEN * H_DIM];
__device__ float g_hn2[S_LEN * H_DIM];
__device__ float g_gate[S_LEN * TOPK];
__device__ int   g_expert[S_LEN * TOPK];
__device__ int   g_slot[S_LEN * TOPK];
__device__ int   g_rowtok[NSLOT];
__device__ int   g_counts[NE];
__device__ int   g_offsets[NE];
__device__ int   g_cursor[NE];
__device__ float g_hmid[(size_t)NSLOT * FF];   // 32 MB
__device__ float g_yslot[(size_t)NSLOT * H_DIM]; // 16 MB

// ---------------- LayerNorm ----------------
// MODE 0: in = xp (input x), out = g_hn.  MODE 1: in = g_x1, out = g_hn2.
template <int MODE>
__global__ __launch_bounds__(256) void ln_kernel(const float* __restrict__ xp,
                                                 const float* __restrict__ w,
                                                 const float* __restrict__ b) {
    const int row = blockIdx.x;
    const int tid = threadIdx.x;
    const float* xin = (MODE == 0) ? xp : g_x1;
    const float* xr = xin + (size_t)row * H_DIM;

    float4 xv = ((const float4*)xr)[tid];
    float s  = xv.x + xv.y + xv.z + xv.w;
    float sq = xv.x * xv.x + xv.y * xv.y + xv.z * xv.z + xv.w * xv.w;
    #pragma unroll
    for (int o = 16; o; o >>= 1) {
        s  += __shfl_xor_sync(0xffffffffu, s, o);
        sq += __shfl_xor_sync(0xffffffffu, sq, o);
    }
    __shared__ float rs[8], rq[8];
    __shared__ float sh_mu, sh_r;
    if ((tid & 31) == 0) { rs[tid >> 5] = s; rq[tid >> 5] = sq; }
    __syncthreads();
    if (tid == 0) {
        float ts = 0.f, tq = 0.f;
        #pragma unroll
        for (int i = 0; i < 8; i++) { ts += rs[i]; tq += rq[i]; }
        float mu = ts * (1.0f / H_DIM);
        float var = tq * (1.0f / H_DIM) - mu * mu;
        sh_mu = mu;
        sh_r = rsqrtf(var + 1e-5f);
    }
    __syncthreads();
    float mu = sh_mu, r = sh_r;
    float4 w4 = ((const float4*)w)[tid];
    float4 b4 = ((const float4*)b)[tid];
    float4 o4;
    o4.x = (xv.x - mu) * r * w4.x + b4.x;
    o4.y = (xv.y - mu) * r * w4.y + b4.y;
    o4.z = (xv.z - mu) * r * w4.z + b4.z;
    o4.w = (xv.w - mu) * r * w4.w + b4.w;
    float* outp = (MODE == 0) ? g_hn : g_hn2;
    ((float4*)(outp + (size_t)row * H_DIM))[tid] = o4;
}

// ---------------- NT SGEMM: C[m][n] = sum_k A[m][k] * B[n][k] + bias[n] (+res) ----
// MODE 0: A=g_hn,   C=g_qkv, N=H3,   K=H_DIM (QKV proj)
// MODE 1: A=g_attn, C=g_x1,  N=H_DIM,K=H_DIM (out proj, +residual x)
template <int MODE>
__global__ __launch_bounds__(256) void gemm_nt_kernel(const float* __restrict__ B,
                                                      const float* __restrict__ bias,
                                                      const float* __restrict__ resid) {
    constexpr int N = (MODE == 0) ? H3 : H_DIM;
    constexpr int K = H_DIM;
    const float* A = (MODE == 0) ? g_hn : g_attn;
    float* C = (MODE == 0) ? g_qkv : g_x1;

    __shared__ float As[8][132];
    __shared__ float Bs[8][132];

    const int m0 = blockIdx.y * 128;
    const int n0 = blockIdx.x * 128;
    const int tid = threadIdx.x;
    const int tx = tid & 15, ty = tid >> 4;

    float acc[8][8];
    #pragma unroll
    for (int i = 0; i < 8; i++)
        #pragma unroll
        for (int j = 0; j < 8; j++) acc[i][j] = 0.f;

    const int lm = tid >> 1;
    const int lk = (tid & 1) * 4;
    const float* Arow = A + (size_t)(m0 + lm) * K + lk;
    const float* Brow = B + (size_t)(n0 + lm) * K + lk;

    for (int k0 = 0; k0 < K; k0 += 8) {
        float4 a = *(const float4*)(Arow + k0);
        float4 bv = *(const float4*)(Brow + k0);
        As[lk + 0][lm] = a.x; As[lk + 1][lm] = a.y; As[lk + 2][lm] = a.z; As[lk + 3][lm] = a.w;
        Bs[lk + 0][lm] = bv.x; Bs[lk + 1][lm] = bv.y; Bs[lk + 2][lm] = bv.z; Bs[lk + 3][lm] = bv.w;
        __syncthreads();
        #pragma unroll
        for (int kk = 0; kk < 8; kk++) {
            float4 a0 = *(const float4*)&As[kk][ty * 4];
            float4 a1 = *(const float4*)&As[kk][64 + ty * 4];
            float4 b0 = *(const float4*)&Bs[kk][tx * 4];
            float4 b1 = *(const float4*)&Bs[kk][64 + tx * 4];
            float ar[8] = {a0.x, a0.y, a0.z, a0.w, a1.x, a1.y, a1.z, a1.w};
            float br[8] = {b0.x, b0.y, b0.z, b0.w, b1.x, b1.y, b1.z, b1.w};
            #pragma unroll
            for (int i = 0; i < 8; i++)
                #pragma unroll
                for (int j = 0; j < 8; j++) acc[i][j] += ar[i] * br[j];
        }
        __syncthreads();
    }

    #pragma unroll
    for (int i = 0; i < 8; i++) {
        int m = m0 + ((i < 4) ? (ty * 4 + i) : (64 + ty * 4 + i - 4));
        #pragma unroll
        for (int jh = 0; jh < 2; jh++) {
            int n = n0 + jh * 64 + tx * 4;
            float4 c;
            c.x = acc[i][jh * 4 + 0];
            c.y = acc[i][jh * 4 + 1];
            c.z = acc[i][jh * 4 + 2];
            c.w = acc[i][jh * 4 + 3];
            c.x += bias[n + 0]; c.y += bias[n + 1]; c.z += bias[n + 2]; c.w += bias[n + 3];
            if (MODE == 1) {
                float4 rr = *(const float4*)(resid + (size_t)m * N + n);
                c.x += rr.x; c.y += rr.y; c.z += rr.z; c.w += rr.w;
            }
            *(float4*)(C + (size_t)m * N + n) = c;
        }
    }
}

// ---------------- Attention (flash-style, fp32) ----------------
#define QT 64
#define KT 32
__global__ __launch_bounds__(128) void attn_kernel() {
    const int head = blockIdx.y;
    const int q0 = blockIdx.x * QT;
    __shared__ float Qs[QT][65];
    __shared__ float Ks[KT][65];
    __shared__ float Vs[KT][65];
    __shared__ float Ps[QT][33];

    const int tid = threadIdx.x;
    const int q = tid >> 1;
    const int hh = tid & 1;

    // load Q tile
    #pragma unroll
    for (int i = 0; i < 8; i++) {
        int flat = (i * 128 + tid) * 4;
        int r = flat >> 6, c = flat & 63;
        float4 v = *(const float4*)(g_qkv + (size_t)(q0 + r) * H3 + head * HD + c);
        Qs[r][c] = v.x; Qs[r][c + 1] = v.y; Qs[r][c + 2] = v.z; Qs[r][c + 3] = v.w;
    }

    float m = -1e30f, l = 0.f;
    float acc[32];
    #pragma unroll
    for (int i = 0; i < 32; i++) acc[i] = 0.f;

    const int kend = q0 + QT;
    for (int k0 = 0; k0 < kend; k0 += KT) {
        __syncthreads();
        #pragma unroll
        for (int i = 0; i < 4; i++) {
            int flat = (i * 128 + tid) * 4;
            int r = flat >> 6, c = flat & 63;
            const float* base = g_qkv + (size_t)(k0 + r) * H3 + head * HD + c;
            float4 kv = *(const float4*)(base + H_DIM);
            float4 vv = *(const float4*)(base + 2 * H_DIM);
            Ks[r][c] = kv.x; Ks[r][c + 1] = kv.y; Ks[r][c + 2] = kv.z; Ks[r][c + 3] = kv.w;
            Vs[r][c] = vv.x; Vs[r][c + 1] = vv.y; Vs[r][c + 2] = vv.z; Vs[r][c + 3] = vv.w;
        }
        __syncthreads();

        // scores for keys hh*16 .. hh*16+15
        float sc[16];
        #pragma unroll
        for (int kk = 0; kk < 16; kk++) sc[kk] = 0.f;
        for (int d = 0; d < 64; d++) {
            float qd = Qs[q][d];
            #pragma unroll
            for (int kk = 0; kk < 16; kk++) sc[kk] += qd * Ks[hh * 16 + kk][d];
        }
        float smax = -1e30f;
        #pragma unroll
        for (int kk = 0; kk < 16; kk++) {
            int kg = k0 + hh * 16 + kk;
            float sv = sc[kk] * 0.125f;
            if (kg > q0 + q) sv = -1e30f;
            sc[kk] = sv;
            smax = fmaxf(smax, sv);
        }
        smax = fmaxf(smax, __shfl_xor_sync(0xffffffffu, smax, 1));
        float mnew = fmaxf(m, smax);
        float corr = __expf(m - mnew);
        float lsum = 0.f;
        #pragma unroll
        for (int kk = 0; kk < 16; kk++) {
            float p = __expf(sc[kk] - mnew);
            Ps[q][hh * 16 + kk] = p;
            lsum += p;
        }
        lsum += __shfl_xor_sync(0xffffffffu, lsum, 1);
        l = l * corr + lsum;
        m = mnew;
        #pragma unroll
        for (int i = 0; i < 32; i++) acc[i] *= corr;
        __syncthreads();
        for (int k = 0; k < KT; k++) {
            float p = Ps[q][k];
            #pragma unroll
            for (int i = 0; i < 32; i++) acc[i] += p * Vs[k][hh * 32 + i];
        }
    }
    float inv = 1.f / l;
    float* outp = g_attn + (size_t)(q0 + q) * H_DIM + head * HD + hh * 32;
    #pragma unroll
    for (int i = 0; i < 32; i++) outp[i] = acc[i] * inv;
}

// ---------------- Router: logits, softmax, top-2, counts ----------------
__global__ __launch_bounds__(128) void router_kernel(const float* __restrict__ rw) {
    const int t = blockIdx.x;
    const int tid = threadIdx.x;
    float accs[NE];
    #pragma unroll
    for (int e = 0; e < NE; e++) accs[e] = 0.f;
    const float* xr = g_hn2 + (size_t)t * H_DIM;
    for (int j = tid; j < H_DIM; j += 128) {
        float xv = xr[j];
        #pragma unroll
        for (int e = 0; e < NE; e++) accs[e] += xv * rw[e * H_DIM + j];
    }
    #pragma unroll
    for (int e = 0; e < NE; e++) {
        #pragma unroll
        for (int o = 16; o; o >>= 1) accs[e] += __shfl_xor_sync(0xffffffffu, accs[e], o);
    }
    __shared__ float wred[NE][4];
    if ((tid & 31) == 0) {
        #pragma unroll
        for (int e = 0; e < NE; e++) wred[e][tid >> 5] = accs[e];
    }
    __syncthreads();
    if (tid == 0) {
        float lg[NE];
        float mx = -1e30f;
        #pragma unroll
        for (int e = 0; e < NE; e++) {
            lg[e] = wred[e][0] + wred[e][1] + wred[e][2] + wred[e][3];
            mx = fmaxf(mx, lg[e]);
        }
        float p[NE], sum = 0.f;
        #pragma unroll
        for (int e = 0; e < NE; e++) { p[e] = expf(lg[e] - mx); sum += p[e]; }
        float inv = 1.f / sum;
        #pragma unroll
        for (int e = 0; e < NE; e++) p[e] *= inv;
        int i0 = 0;
        #pragma unroll
        for (int e = 1; e < NE; e++) if (lg[e] > lg[i0]) i0 = e;
        int i1 = (i0 == 0) ? 1 : 0;
        #pragma unroll
        for (int e = 0; e < NE; e++) if (e != i0 && lg[e] > lg[i1]) i1 = e;
        g_expert[t * 2 + 0] = i0; g_gate[t * 2 + 0] = p[i0];
        g_expert[t * 2 + 1] = i1; g_gate[t * 2 + 1] = p[i1];
        atomicAdd(&g_counts[i0], 1);
        atomicAdd(&g_counts[i1], 1);
    }
}

__global__ void zero_kernel() {
    int i = threadIdx.x;
    if (i < NE) g_counts[i] = 0;
}

__global__ void scan_kernel() {
    if (threadIdx.x == 0) {
        int o = 0;
        for (int e = 0; e < NE; e++) { g_offsets[e] = o; o += g_counts[e]; g_cursor[e] = 0; }
    }
}

__global__ void fill_kernel() {
    int t = blockIdx.x * blockDim.x + threadIdx.x;
    if (t >= S_LEN) return;
    #pragma unroll
    for (int k = 0; k < TOPK; k++) {
        int e = g_expert[t * 2 + k];
        int pos = g_offsets[e] + atomicAdd(&g_cursor[e], 1);
        g_rowtok[pos] = t;
        g_slot[t * 2 + k] = pos;
    }
}

// ---------------- Grouped MoE GEMM (NN) ----------------
// STAGE 1: A = gathered g_hn2 [Me, 1024], B = w1[e] [1024, 2048], GELU -> g_hmid
// STAGE 2: A = g_hmid rows      [Me, 2048], B = w2[e] [2048, 1024]        -> g_yslot
template <int STAGE>
__global__ __launch_bounds__(256) void moe_gemm_kernel(const float* __restrict__ Bsrc) {
    const int e = blockIdx.z;
    const int Me = g_counts[e];
    const int m0 = blockIdx.y * 128;
    if (m0 >= Me) return;
    const int off = g_offsets[e];
    constexpr int Kd = (STAGE == 1) ? H_DIM : FF;
    constexpr int Nn = (STAGE == 1) ? FF : H_DIM;
    const float* B = Bsrc + (size_t)e * Kd * Nn;
    const int n0 = blockIdx.x * 128;

    __shared__ float As[8][132];
    __shared__ float Bs[8][132];

    const int tid = threadIdx.x;
    const int tx = tid & 15, ty = tid >> 4;

    float acc[8][8];
    #pragma unroll
    for (int i = 0; i < 8; i++)
        #pragma unroll
        for (int j = 0; j < 8; j++) acc[i][j] = 0.f;

    const int lm = tid >> 1;
    const int lk = (tid & 1) * 4;
    int mrow = m0 + lm;
    if (mrow >= Me) mrow = 0;
    const float* Arow;
    if (STAGE == 1) {
        int tok = g_rowtok[off + mrow];
        Arow = g_hn2 + (size_t)tok * H_DIM + lk;
    } else {
        Arow = g_hmid + (size_t)(off + mrow) * FF + lk;
    }
    const int bk = tid >> 5;
    const int bn = (tid & 31) * 4;
    const float* Bld = B + (size_t)bk * Nn + n0 + bn;

    for (int k0 = 0; k0 < Kd; k0 += 8) {
        float4 a = *(const float4*)(Arow + k0);
        float4 bv = *(const float4*)(Bld + (size_t)k0 * Nn);
        As[lk + 0][lm] = a.x; As[lk + 1][lm] = a.y; As[lk + 2][lm] = a.z; As[lk + 3][lm] = a.w;
        *(float4*)&Bs[bk][bn] = bv;
        __syncthreads();
        #pragma unroll
        for (int kk = 0; kk < 8; kk++) {
            float4 a0 = *(const float4*)&As[kk][ty * 4];
            float4 a1 = *(const float4*)&As[kk][64 + ty * 4];
            float4 b0 = *(const float4*)&Bs[kk][tx * 4];
            float4 b1 = *(const float4*)&Bs[kk][64 + tx * 4];
            float ar[8] = {a0.x, a0.y, a0.z, a0.w, a1.x, a1.y, a1.z, a1.w};
            float br[8] = {b0.x, b0.y, b0.z, b0.w, b1.x, b1.y, b1.z, b1.w};
            #pragma unroll
            for (int i = 0; i < 8; i++)
                #pragma unroll
                for (int j = 0; j < 8; j++) acc[i][j] += ar[i] * br[j];
        }
        __syncthreads();
    }

    #pragma unroll
    for (int i = 0; i < 8; i++) {
        int mloc = (i < 4) ? (ty * 4 + i) : (64 + ty * 4 + i - 4);
        int m = m0 + mloc;
        if (m >= Me) continue;
        #pragma unroll
        for (int jh = 0; jh < 2; jh++) {
            int n = n0 + jh * 64 + tx * 4;
            float4 c;
            c.x = acc[i][jh * 4 + 0];
            c.y = acc[i][jh * 4 + 1];
            c.z = acc[i][jh * 4 + 2];
            c.w = acc[i][jh * 4 + 3];
            if (STAGE == 1) {
                c.x = 0.5f * c.x * (1.f + erff(c.x * 0.70710678118654752f));
                c.y = 0.5f * c.y * (1.f + erff(c.y * 0.70710678118654752f));
                c.z = 0.5f * c.z * (1.f + erff(c.z * 0.70710678118654752f));
                c.w = 0.5f * c.w * (1.f + erff(c.w * 0.70710678118654752f));
                *(float4*)(g_hmid + (size_t)(off + m) * FF + n) = c;
            } else {
                *(float4*)(g_yslot + (size_t)(off + m) * H_DIM + n) = c;
            }
        }
    }
}

// ---------------- Combine: out = x1 + g0*y0 + g1*y1 ----------------
__global__ __launch_bounds__(256) void combine_kernel(float* __restrict__ out) {
    const int t = blockIdx.x;
    const int s0 = g_slot[t * 2 + 0];
    const int s1 = g_slot[t * 2 + 1];
    const float g0 = g_gate[t * 2 + 0];
    const float g1 = g_gate[t * 2 + 1];
    const float4* y0 = (const float4*)(g_yslot + (size_t)s0 * H_DIM);
    const float4* y1 = (const float4*)(g_yslot + (size_t)s1 * H_DIM);
    const float4* x1 = (const float4*)(g_x1 + (size_t)t * H_DIM);
    float4* o = (float4*)(out + (size_t)t * H_DIM);
    int i = threadIdx.x;
    float4 a = x1[i], b = y0[i], c = y1[i];
    float4 r;
    r.x = a.x + g0 * b.x + g1 * c.x;
    r.y = a.y + g0 * b.y + g1 * c.y;
    r.z = a.z + g0 * b.z + g1 * c.z;
    r.w = a.w + g0 * b.w + g1 * c.w;
    o[i] = r;
}

// ---------------- launch ----------------
extern "C" void kernel_launch(void* const* d_in, const int* in_sizes, int n_in,
                              void* d_out, int out_size) {
    (void)in_sizes; (void)n_in; (void)out_size;
    const float* x          = (const float*)d_in[0];
    const float* ln1_w      = (const float*)d_in[1];
    const float* ln1_b      = (const float*)d_in[2];
    const float* in_proj_w  = (const float*)d_in[3];
    const float* in_proj_b  = (const float*)d_in[4];
    const float* out_proj_w = (const float*)d_in[5];
    const float* out_proj_b = (const float*)d_in[6];
    const float* ln2_w      = (const float*)d_in[7];
    const float* ln2_b      = (const float*)d_in[8];
    const float* router_w   = (const float*)d_in[9];
    const float* w1         = (const float*)d_in[10];
    const float* w2         = (const float*)d_in[11];
    float* out = (float*)d_out;

    ln_kernel<0><<<S_LEN, 256>>>(x, ln1_w, ln1_b);
    gemm_nt_kernel<0><<<dim3(H3 / 128, S_LEN / 128), 256>>>(in_proj_w, in_proj_b, nullptr);
    attn_kernel<<<dim3(S_LEN / QT, NH), 128>>>();
    gemm_nt_kernel<1><<<dim3(H_DIM / 128, S_LEN / 128), 256>>>(out_proj_w, out_proj_b, x);
    ln_kernel<1><<<S_LEN, 256>>>(nullptr, ln2_w, ln2_b);
    zero_kernel<<<1, 32>>>();
    router_kernel<<<S_LEN, 128>>>(router_w);
    scan_kernel<<<1, 32>>>();
    fill_kernel<<<S_LEN / 256, 256>>>();
    moe_gemm_kernel<1><<<dim3(FF / 128, NSLOT / 128, NE), 256>>>(w1);
    moe_gemm_kernel<2><<<dim3(H_DIM / 128, NSLOT / 128, NE), 256>>>(w2);
    combine_kernel<<<S_LEN, 256>>>(out);
}

// round 2
// speedup vs baseline: 1.5067x; 1.5067x over previous
#include <cuda_runtime.h>
#include <cstdint>
#include <math.h>

#define S_LEN 2048
#define H_DIM 1024
#define NH 16
#define HD 64
#define H3 3072
#define NE 8
#define TOPK 2
#define FF 2048
#define NSLOT (S_LEN * TOPK)

// ---------------- scratch (static device globals; no allocation) ----------------
__device__ float g_hn[S_LEN * H_DIM];
__device__ float g_qkv[S_LEN * H3];
__device__ float g_attn[S_LEN * H_DIM];
__device__ float g_x1[S_LEN * H_DIM];
__device__ float g_hn2[S_LEN * H_DIM];
__device__ float g_gate[S_LEN * TOPK];
__device__ int   g_expert[S_LEN * TOPK];
__device__ int   g_slot[S_LEN * TOPK];
__device__ int   g_rowtok[NSLOT];
__device__ int   g_counts[NE];
__device__ int   g_offsets[NE];
__device__ int   g_cursor[NE];
__device__ float g_hmid[(size_t)NSLOT * FF];     // 32 MB
__device__ float g_yslot[(size_t)NSLOT * H_DIM]; // 16 MB

// ---------------- PTX helpers ----------------
__device__ __forceinline__ uint32_t sof(const void* p) {
    return (uint32_t)__cvta_generic_to_shared(p);
}
__device__ __forceinline__ void cp16(uint32_t s, const void* g) {
    asm volatile("cp.async.cg.shared.global [%0], [%1], 16;\n" :: "r"(s), "l"(g));
}
__device__ __forceinline__ void cp_commit() { asm volatile("cp.async.commit_group;\n"); }
template <int N>
__device__ __forceinline__ void cp_wait() { asm volatile("cp.async.wait_group %0;\n" :: "n"(N)); }

__device__ __forceinline__ uint32_t f2tf(float x) {
    uint32_t r;
    asm("cvt.rna.tf32.f32 %0, %1;" : "=r"(r) : "f"(x));
    return r;
}
__device__ __forceinline__ void mma_tf32(float* c, const uint32_t* a, const uint32_t* b) {
    asm volatile(
        "mma.sync.aligned.m16n8k8.row.col.f32.tf32.tf32.f32 "
        "{%0,%1,%2,%3}, {%4,%5,%6,%7}, {%8,%9}, {%0,%1,%2,%3};\n"
        : "+f"(c[0]), "+f"(c[1]), "+f"(c[2]), "+f"(c[3])
        : "r"(a[0]), "r"(a[1]), "r"(a[2]), "r"(a[3]), "r"(b[0]), "r"(b[1]));
}

// ---------------- LayerNorm ----------------
template <int MODE>
__global__ __launch_bounds__(256) void ln_kernel(const float* __restrict__ xp,
                                                 const float* __restrict__ w,
                                                 const float* __restrict__ b) {
    const int row = blockIdx.x;
    const int tid = threadIdx.x;
    const float* xin = (MODE == 0) ? xp : g_x1;
    const float* xr = xin + (size_t)row * H_DIM;

    float4 xv = ((const float4*)xr)[tid];
    float s  = xv.x + xv.y + xv.z + xv.w;
    float sq = xv.x * xv.x + xv.y * xv.y + xv.z * xv.z + xv.w * xv.w;
    #pragma unroll
    for (int o = 16; o; o >>= 1) {
        s  += __shfl_xor_sync(0xffffffffu, s, o);
        sq += __shfl_xor_sync(0xffffffffu, sq, o);
    }
    __shared__ float rs[8], rq[8];
    __shared__ float sh_mu, sh_r;
    if ((tid & 31) == 0) { rs[tid >> 5] = s; rq[tid >> 5] = sq; }
    __syncthreads();
    if (tid == 0) {
        float ts = 0.f, tq = 0.f;
        #pragma unroll
        for (int i = 0; i < 8; i++) { ts += rs[i]; tq += rq[i]; }
        float mu = ts * (1.0f / H_DIM);
        float var = tq * (1.0f / H_DIM) - mu * mu;
        sh_mu = mu;
        sh_r = rsqrtf(var + 1e-5f);
    }
    __syncthreads();
    float mu = sh_mu, r = sh_r;
    float4 w4 = ((const float4*)w)[tid];
    float4 b4 = ((const float4*)b)[tid];
    float4 o4;
    o4.x = (xv.x - mu) * r * w4.x + b4.x;
    o4.y = (xv.y - mu) * r * w4.y + b4.y;
    o4.z = (xv.z - mu) * r * w4.z + b4.z;
    o4.w = (xv.w - mu) * r * w4.w + b4.w;
    float* outp = (MODE == 0) ? g_hn : g_hn2;
    ((float4*)(outp + (size_t)row * H_DIM))[tid] = o4;
}

// ---------------- NT GEMM via tf32 tensor cores ----------------
// C[m][n] = sum_k A[m][k] * W[n][k] + bias[n] (+resid)
// MODE 0: A=g_hn,   C=g_qkv, N=H3   (QKV proj)
// MODE 1: A=g_attn, C=g_x1,  N=H_DIM (out proj, +resid)
template <int MODE>
__global__ __launch_bounds__(256) void gemm_nt_tc(const float* __restrict__ Bw,
                                                  const float* __restrict__ bias,
                                                  const float* __restrict__ resid) {
    constexpr int N = (MODE == 0) ? H3 : H_DIM;
    constexpr int K = H_DIM;
    constexpr int NCH = K / 16;
    const float* A = (MODE == 0) ? g_hn : g_attn;
    float* C = (MODE == 0) ? g_qkv : g_x1;

    __shared__ float As[2][128][20];
    __shared__ float Bs[2][128][20];

    const int m0 = blockIdx.y * 128;
    const int n0 = blockIdx.x * 128;
    const int tid = threadIdx.x;
    const int lane = tid & 31;
    const int wid = tid >> 5;
    const int wm = (wid >> 2) * 64;
    const int wn = (wid & 3) * 32;
    const int g = lane >> 2;
    const int t = lane & 3;

    // loader mapping: 2 rows of A, 2 rows of B per thread, 16B each
    const int lr = tid >> 2;           // 0..63
    const int lk = (tid & 3) * 4;      // 0,4,8,12
    const float* Ap0 = A + (size_t)(m0 + lr) * K + lk;
    const float* Ap1 = A + (size_t)(m0 + lr + 64) * K + lk;
    const float* Bp0 = Bw + (size_t)(n0 + lr) * K + lk;
    const float* Bp1 = Bw + (size_t)(n0 + lr + 64) * K + lk;

    float acc[4][4][4];
    #pragma unroll
    for (int i = 0; i < 4; i++)
        #pragma unroll
        for (int j = 0; j < 4; j++)
            #pragma unroll
            for (int r = 0; r < 4; r++) acc[i][j][r] = 0.f;

    // prologue: chunk 0
    {
        cp16(sof(&As[0][lr][lk]), Ap0);
        cp16(sof(&As[0][lr + 64][lk]), Ap1);
        cp16(sof(&Bs[0][lr][lk]), Bp0);
        cp16(sof(&Bs[0][lr + 64][lk]), Bp1);
        cp_commit();
    }

    for (int c = 0; c < NCH; c++) {
        __syncthreads();   // all warps done with compute c-1 (buffer (c+1)&1 free)
        if (c + 1 < NCH) {
            int s = (c + 1) & 1;
            int k0 = (c + 1) * 16;
            cp16(sof(&As[s][lr][lk]), Ap0 + k0);
            cp16(sof(&As[s][lr + 64][lk]), Ap1 + k0);
            cp16(sof(&Bs[s][lr][lk]), Bp0 + k0);
            cp16(sof(&Bs[s][lr + 64][lk]), Bp1 + k0);
            cp_commit();
            cp_wait<1>();
        } else {
            cp_wait<0>();
        }
        __syncthreads();   // chunk c visible to all
        const int s = c & 1;
        #pragma unroll
        for (int kk = 0; kk < 16; kk += 8) {
            uint32_t af[4][4], bf[4][2];
            #pragma unroll
            for (int i = 0; i < 4; i++) {
                int r = wm + i * 16 + g;
                af[i][0] = f2tf(As[s][r][kk + t]);
                af[i][1] = f2tf(As[s][r + 8][kk + t]);
                af[i][2] = f2tf(As[s][r][kk + t + 4]);
                af[i][3] = f2tf(As[s][r + 8][kk + t + 4]);
            }
            #pragma unroll
            for (int j = 0; j < 4; j++) {
                int n = wn + j * 8 + g;
                bf[j][0] = f2tf(Bs[s][n][kk + t]);
                bf[j][1] = f2tf(Bs[s][n][kk + t + 4]);
            }
            #pragma unroll
            for (int i = 0; i < 4; i++)
                #pragma unroll
                for (int j = 0; j < 4; j++)
                    mma_tf32(acc[i][j], af[i], bf[j]);
        }
    }

    // epilogue
    #pragma unroll
    for (int i = 0; i < 4; i++) {
        int r0 = m0 + wm + i * 16 + g;
        #pragma unroll
        for (int j = 0; j < 4; j++) {
            int col = n0 + wn + j * 8 + 2 * t;
            float bx = bias[col], by = bias[col + 1];
            float2 v0, v1;
            v0.x = acc[i][j][0] + bx; v0.y = acc[i][j][1] + by;
            v1.x = acc[i][j][2] + bx; v1.y = acc[i][j][3] + by;
            if (MODE == 1) {
                float2 ra = *(const float2*)(resid + (size_t)r0 * N + col);
                float2 rb = *(const float2*)(resid + (size_t)(r0 + 8) * N + col);
                v0.x += ra.x; v0.y += ra.y;
                v1.x += rb.x; v1.y += rb.y;
            }
            *(float2*)(C + (size_t)r0 * N + col) = v0;
            *(float2*)(C + (size_t)(r0 + 8) * N + col) = v1;
        }
    }
}

// ---------------- Attention (flash-style, fp32) ----------------
#define QT 64
#define KT 32
__global__ __launch_bounds__(128) void attn_kernel() {
    const int head = blockIdx.y;
    const int q0 = blockIdx.x * QT;
    __shared__ float Qs[QT][65];
    __shared__ float Ks[KT][65];
    __shared__ float Vs[KT][65];
    __shared__ float Ps[QT][33];

    const int tid = threadIdx.x;
    const int q = tid >> 1;
    const int hh = tid & 1;

    #pragma unroll
    for (int i = 0; i < 8; i++) {
        int flat = (i * 128 + tid) * 4;
        int r = flat >> 6, c = flat & 63;
        float4 v = *(const float4*)(g_qkv + (size_t)(q0 + r) * H3 + head * HD + c);
        Qs[r][c] = v.x; Qs[r][c + 1] = v.y; Qs[r][c + 2] = v.z; Qs[r][c + 3] = v.w;
    }

    float m = -1e30f, l = 0.f;
    float acc[32];
    #pragma unroll
    for (int i = 0; i < 32; i++) acc[i] = 0.f;

    const int kend = q0 + QT;
    for (int k0 = 0; k0 < kend; k0 += KT) {
        __syncthreads();
        #pragma unroll
        for (int i = 0; i < 4; i++) {
            int flat = (i * 128 + tid) * 4;
            int r = flat >> 6, c = flat & 63;
            const float* base = g_qkv + (size_t)(k0 + r) * H3 + head * HD + c;
            float4 kv = *(const float4*)(base + H_DIM);
            float4 vv = *(const float4*)(base + 2 * H_DIM);
            Ks[r][c] = kv.x; Ks[r][c + 1] = kv.y; Ks[r][c + 2] = kv.z; Ks[r][c + 3] = kv.w;
            Vs[r][c] = vv.x; Vs[r][c + 1] = vv.y; Vs[r][c + 2] = vv.z; Vs[r][c + 3] = vv.w;
        }
        __syncthreads();

        float sc[16];
        #pragma unroll
        for (int kk = 0; kk < 16; kk++) sc[kk] = 0.f;
        for (int d = 0; d < 64; d++) {
            float qd = Qs[q][d];
            #pragma unroll
            for (int kk = 0; kk < 16; kk++) sc[kk] += qd * Ks[hh * 16 + kk][d];
        }
        float smax = -1e30f;
        #pragma unroll
        for (int kk = 0; kk < 16; kk++) {
            int kg = k0 + hh * 16 + kk;
            float sv = sc[kk] * 0.125f;
            if (kg > q0 + q) sv = -1e30f;
            sc[kk] = sv;
            smax = fmaxf(smax, sv);
        }
        smax = fmaxf(smax, __shfl_xor_sync(0xffffffffu, smax, 1));
        float mnew = fmaxf(m, smax);
        float corr = __expf(m - mnew);
        float lsum = 0.f;
        #pragma unroll
        for (int kk = 0; kk < 16; kk++) {
            float p = __expf(sc[kk] - mnew);
            Ps[q][hh * 16 + kk] = p;
            lsum += p;
        }
        lsum += __shfl_xor_sync(0xffffffffu, lsum, 1);
        l = l * corr + lsum;
        m = mnew;
        #pragma unroll
        for (int i = 0; i < 32; i++) acc[i] *= corr;
        __syncthreads();
        for (int k = 0; k < KT; k++) {
            float p = Ps[q][k];
            #pragma unroll
            for (int i = 0; i < 32; i++) acc[i] += p * Vs[k][hh * 32 + i];
        }
    }
    float inv = 1.f / l;
    float* outp = g_attn + (size_t)(q0 + q) * H_DIM + head * HD + hh * 32;
    #pragma unroll
    for (int i = 0; i < 32; i++) outp[i] = acc[i] * inv;
}

// ---------------- Router ----------------
__global__ __launch_bounds__(128) void router_kernel(const float* __restrict__ rw) {
    const int t = blockIdx.x;
    const int tid = threadIdx.x;
    float accs[NE];
    #pragma unroll
    for (int e = 0; e < NE; e++) accs[e] = 0.f;
    const float* xr = g_hn2 + (size_t)t * H_DIM;
    for (int j = tid; j < H_DIM; j += 128) {
        float xv = xr[j];
        #pragma unroll
        for (int e = 0; e < NE; e++) accs[e] += xv * rw[e * H_DIM + j];
    }
    #pragma unroll
    for (int e = 0; e < NE; e++) {
        #pragma unroll
        for (int o = 16; o; o >>= 1) accs[e] += __shfl_xor_sync(0xffffffffu, accs[e], o);
    }
    __shared__ float wred[NE][4];
    if ((tid & 31) == 0) {
        #pragma unroll
        for (int e = 0; e < NE; e++) wred[e][tid >> 5] = accs[e];
    }
    __syncthreads();
    if (tid == 0) {
        float lg[NE];
        float mx = -1e30f;
        #pragma unroll
        for (int e = 0; e < NE; e++) {
            lg[e] = wred[e][0] + wred[e][1] + wred[e][2] + wred[e][3];
            mx = fmaxf(mx, lg[e]);
        }
        float p[NE], sum = 0.f;
        #pragma unroll
        for (int e = 0; e < NE; e++) { p[e] = expf(lg[e] - mx); sum += p[e]; }
        float inv = 1.f / sum;
        #pragma unroll
        for (int e = 0; e < NE; e++) p[e] *= inv;
        int i0 = 0;
        #pragma unroll
        for (int e = 1; e < NE; e++) if (lg[e] > lg[i0]) i0 = e;
        int i1 = (i0 == 0) ? 1 : 0;
        #pragma unroll
        for (int e = 0; e < NE; e++) if (e != i0 && lg[e] > lg[i1]) i1 = e;
        g_expert[t * 2 + 0] = i0; g_gate[t * 2 + 0] = p[i0];
        g_expert[t * 2 + 1] = i1; g_gate[t * 2 + 1] = p[i1];
        atomicAdd(&g_counts[i0], 1);
        atomicAdd(&g_counts[i1], 1);
    }
}

__global__ void zero_kernel() {
    int i = threadIdx.x;
    if (i < NE) g_counts[i] = 0;
}

__global__ void scan_kernel() {
    if (threadIdx.x == 0) {
        int o = 0;
        for (int e = 0; e < NE; e++) { g_offsets[e] = o; o += g_counts[e]; g_cursor[e] = 0; }
    }
}

__global__ void fill_kernel() {
    int t = blockIdx.x * blockDim.x + threadIdx.x;
    if (t >= S_LEN) return;
    #pragma unroll
    for (int k = 0; k < TOPK; k++) {
        int e = g_expert[t * 2 + k];
        int pos = g_offsets[e] + atomicAdd(&g_cursor[e], 1);
        g_rowtok[pos] = t;
        g_slot[t * 2 + k] = pos;
    }
}

// ---------------- Grouped MoE GEMM (NN) via tf32 tensor cores ----------------
// STAGE 1: A = gathered g_hn2 [Me,1024], B = w1[e] [1024,2048], GELU -> g_hmid
// STAGE 2: A = g_hmid rows    [Me,2048], B = w2[e] [2048,1024]        -> g_yslot
template <int STAGE>
__global__ __launch_bounds__(256) void moe_gemm_tc(const float* __restrict__ Bsrc) {
    const int e = blockIdx.z;
    const int Me = g_counts[e];
    const int m0 = blockIdx.y * 128;
    if (m0 >= Me) return;
    const int off = g_offsets[e];
    constexpr int Kd = (STAGE == 1) ? H_DIM : FF;
    constexpr int Nn = (STAGE == 1) ? FF : H_DIM;
    constexpr int NCH = Kd / 16;
    const float* B = Bsrc + (size_t)e * Kd * Nn;
    const int n0 = blockIdx.x * 128;

    __shared__ float As[2][128][20];
    __shared__ float Bs[2][16][136];

    const int tid = threadIdx.x;
    const int lane = tid & 31;
    const int wid = tid >> 5;
    const int wm = (wid >> 2) * 64;
    const int wn = (wid & 3) * 32;
    const int g = lane >> 2;
    const int t = lane & 3;

    // A loader: 2 rows per thread
    const int lr = tid >> 2;
    const int lk = (tid & 3) * 4;
    int mra = m0 + lr;       if (mra > Me - 1) mra = Me - 1;
    int mrb = m0 + lr + 64;  if (mrb > Me - 1) mrb = Me - 1;
    const float* Ap0;
    const float* Ap1;
    if (STAGE == 1) {
        Ap0 = g_hn2 + (size_t)g_rowtok[off + mra] * H_DIM + lk;
        Ap1 = g_hn2 + (size_t)g_rowtok[off + mrb] * H_DIM + lk;
    } else {
        Ap0 = g_hmid + (size_t)(off + mra) * FF + lk;
        Ap1 = g_hmid + (size_t)(off + mrb) * FF + lk;
    }
    // B loader: 2 chunks per thread; k = id>>5 (0..15), nc = (id&31)*4
    const int bk0 = tid >> 5;          // 0..7
    const int bnc = (tid & 31) * 4;
    const float* Bp0 = B + (size_t)bk0 * Nn + n0 + bnc;
    const float* Bp1 = B + (size_t)(bk0 + 8) * Nn + n0 + bnc;

    float acc[4][4][4];
    #pragma unroll
    for (int i = 0; i < 4; i++)
        #pragma unroll
        for (int j = 0; j < 4; j++)
            #pragma unroll
            for (int r = 0; r < 4; r++) acc[i][j][r] = 0.f;

    {
        cp16(sof(&As[0][lr][lk]), Ap0);
        cp16(sof(&As[0][lr + 64][lk]), Ap1);
        cp16(sof(&Bs[0][bk0][bnc]), Bp0);
        cp16(sof(&Bs[0][bk0 + 8][bnc]), Bp1);
        cp_commit();
    }

    for (int c = 0; c < NCH; c++) {
        __syncthreads();
        if (c + 1 < NCH) {
            int s = (c + 1) & 1;
            int k0 = (c + 1) * 16;
            cp16(sof(&As[s][lr][lk]), Ap0 + k0);
            cp16(sof(&As[s][lr + 64][lk]), Ap1 + k0);
            cp16(sof(&Bs[s][bk0][bnc]), Bp0 + (size_t)k0 * Nn);
            cp16(sof(&Bs[s][bk0 + 8][bnc]), Bp1 + (size_t)k0 * Nn);
            cp_commit();
            cp_wait<1>();
        } else {
            cp_wait<0>();
        }
        __syncthreads();
        const int s = c & 1;
        #pragma unroll
        for (int kk = 0; kk < 16; kk += 8) {
            uint32_t af[4][4], bf[4][2];
            #pragma unroll
            for (int i = 0; i < 4; i++) {
                int r = wm + i * 16 + g;
                af[i][0] = f2tf(As[s][r][kk + t]);
                af[i][1] = f2tf(As[s][r + 8][kk + t]);
                af[i][2] = f2tf(As[s][r][kk + t + 4]);
                af[i][3] = f2tf(As[s][r + 8][kk + t + 4]);
            }
            #pragma unroll
            for (int j = 0; j < 4; j++) {
                int n = wn + j * 8 + g;
                bf[j][0] = f2tf(Bs[s][kk + t][n]);
                bf[j][1] = f2tf(Bs[s][kk + t + 4][n]);
            }
            #pragma unroll
            for (int i = 0; i < 4; i++)
                #pragma unroll
                for (int j = 0; j < 4; j++)
                    mma_tf32(acc[i][j], af[i], bf[j]);
        }
    }

    #pragma unroll
    for (int i = 0; i < 4; i++) {
        int rloc0 = wm + i * 16 + g;
        #pragma unroll
        for (int j = 0; j < 4; j++) {
            int col = n0 + wn + j * 8 + 2 * t;
            #pragma unroll
            for (int half = 0; half < 2; half++) {
                int mloc = rloc0 + half * 8;
                int m = m0 + mloc;
                if (m >= Me) continue;
                float2 v;
                v.x = acc[i][j][half * 2 + 0];
                v.y = acc[i][j][half * 2 + 1];
                if (STAGE == 1) {
                    v.x = 0.5f * v.x * (1.f + erff(v.x * 0.70710678118654752f));
                    v.y = 0.5f * v.y * (1.f + erff(v.y * 0.70710678118654752f));
                    *(float2*)(g_hmid + (size_t)(off + m) * FF + col) = v;
                } else {
                    *(float2*)(g_yslot + (size_t)(off + m) * H_DIM + col) = v;
                }
            }
        }
    }
}

// ---------------- Combine: out = x1 + g0*y0 + g1*y1 ----------------
__global__ __launch_bounds__(256) void combine_kernel(float* __restrict__ out) {
    const int t = blockIdx.x;
    const int s0 = g_slot[t * 2 + 0];
    const int s1 = g_slot[t * 2 + 1];
    const float g0 = g_gate[t * 2 + 0];
    const float g1 = g_gate[t * 2 + 1];
    const float4* y0 = (const float4*)(g_yslot + (size_t)s0 * H_DIM);
    const float4* y1 = (const float4*)(g_yslot + (size_t)s1 * H_DIM);
    const float4* x1 = (const float4*)(g_x1 + (size_t)t * H_DIM);
    float4* o = (float4*)(out + (size_t)t * H_DIM);
    int i = threadIdx.x;
    float4 a = x1[i], b = y0[i], c = y1[i];
    float4 r;
    r.x = a.x + g0 * b.x + g1 * c.x;
    r.y = a.y + g0 * b.y + g1 * c.y;
    r.z = a.z + g0 * b.z + g1 * c.z;
    r.w = a.w + g0 * b.w + g1 * c.w;
    o[i] = r;
}

// ---------------- launch ----------------
extern "C" void kernel_launch(void* const* d_in, const int* in_sizes, int n_in,
                              void* d_out, int out_size) {
    (void)in_sizes; (void)n_in; (void)out_size;
    const float* x          = (const float*)d_in[0];
    const float* ln1_w      = (const float*)d_in[1];
    const float* ln1_b      = (const float*)d_in[2];
    const float* in_proj_w  = (const float*)d_in[3];
    const float* in_proj_b  = (const float*)d_in[4];
    const float* out_proj_w = (const float*)d_in[5];
    const float* out_proj_b = (const float*)d_in[6];
    const float* ln2_w      = (const float*)d_in[7];
    const float* ln2_b      = (const float*)d_in[8];
    const float* router_w   = (const float*)d_in[9];
    const float* w1         = (const float*)d_in[10];
    const float* w2         = (const float*)d_in[11];
    float* out = (float*)d_out;

    ln_kernel<0><<<S_LEN, 256>>>(x, ln1_w, ln1_b);
    gemm_nt_tc<0><<<dim3(H3 / 128, S_LEN / 128), 256>>>(in_proj_w, in_proj_b, nullptr);
    attn_kernel<<<dim3(S_LEN / QT, NH), 128>>>();
    gemm_nt_tc<1><<<dim3(H_DIM / 128, S_LEN / 128), 256>>>(out_proj_w, out_proj_b, x);
    ln_kernel<1><<<S_LEN, 256>>>(nullptr, ln2_w, ln2_b);
    zero_kernel<<<1, 32>>>();
    router_kernel<<<S_LEN, 128>>>(router_w);
    scan_kernel<<<1, 32>>>();
    fill_kernel<<<S_LEN / 256, 256>>>();
    moe_gemm_tc<1><<<dim3(FF / 128, S_LEN / 128, NE), 256>>>(w1);
    moe_gemm_tc<2><<<dim3(H_DIM / 128, S_LEN / 128, NE), 256>>>(w2);
    combine_kernel<<<S_LEN, 256>>>(out);
}

// round 4
// speedup vs baseline: 3.7065x; 2.4600x over previous
#include <cuda_runtime.h>
#include <cstdint>
#include <math.h>

#define S_LEN 2048
#define H_DIM 1024
#define NH 16
#define HD 64
#define H3 3072
#define NE 8
#define TOPK 2
#define FF 2048
#define NSLOT (S_LEN * TOPK)

// ---------------- scratch ----------------
__device__ float g_hn[S_LEN * H_DIM];
__device__ float g_qkv[S_LEN * H3];
__device__ float g_attn[S_LEN * H_DIM];
__device__ float g_x1[S_LEN * H_DIM];
__device__ float g_hn2[S_LEN * H_DIM];
__device__ float g_gate[S_LEN * TOPK];
__device__ int   g_expert[S_LEN * TOPK];
__device__ int   g_slot[S_LEN * TOPK];
__device__ int   g_rowtok[NSLOT];
__device__ int   g_counts[NE];
__device__ int   g_offsets[NE];
__device__ int   g_cursor[NE];
__device__ float g_hmid[(size_t)NSLOT * FF];
__device__ float g_yslot[(size_t)NSLOT * H_DIM];

// ---------------- PTX helpers ----------------
__device__ __forceinline__ uint32_t sof(const void* p) {
    return (uint32_t)__cvta_generic_to_shared(p);
}
__device__ __forceinline__ void cp16(uint32_t s, const void* g) {
    asm volatile("cp.async.cg.shared.global [%0], [%1], 16;\n" :: "r"(s), "l"(g));
}
__device__ __forceinline__ void cp_commit() { asm volatile("cp.async.commit_group;\n"); }
template <int N>
__device__ __forceinline__ void cp_wait() { asm volatile("cp.async.wait_group %0;\n" :: "n"(N)); }

// round-to-nearest tf32 conversion (unbiased — REQUIRED for K=1024 sums)
__device__ __forceinline__ uint32_t f2tf(float x) {
    uint32_t r;
    asm("cvt.rna.tf32.f32 %0, %1;" : "=r"(r) : "f"(x));
    return r;
}
__device__ __forceinline__ void mma_tf32(float* c, const uint32_t* a, const uint32_t* b) {
    asm volatile(
        "mma.sync.aligned.m16n8k8.row.col.f32.tf32.tf32.f32 "
        "{%0,%1,%2,%3}, {%4,%5,%6,%7}, {%8,%9}, {%0,%1,%2,%3};\n"
        : "+f"(c[0]), "+f"(c[1]), "+f"(c[2]), "+f"(c[3])
        : "r"(a[0]), "r"(a[1]), "r"(a[2]), "r"(a[3]), "r"(b[0]), "r"(b[1]));
}

// ---------------- LayerNorm ----------------
template <int MODE>
__global__ __launch_bounds__(256) void ln_kernel(const float* __restrict__ xp,
                                                 const float* __restrict__ w,
                                                 const float* __restrict__ b) {
    const int row = blockIdx.x;
    const int tid = threadIdx.x;
    const float* xin = (MODE == 0) ? xp : g_x1;
    const float* xr = xin + (size_t)row * H_DIM;

    float4 xv = ((const float4*)xr)[tid];
    float s  = xv.x + xv.y + xv.z + xv.w;
    float sq = xv.x * xv.x + xv.y * xv.y + xv.z * xv.z + xv.w * xv.w;
    #pragma unroll
    for (int o = 16; o; o >>= 1) {
        s  += __shfl_xor_sync(0xffffffffu, s, o);
        sq += __shfl_xor_sync(0xffffffffu, sq, o);
    }
    __shared__ float rs[8], rq[8];
    __shared__ float sh_mu, sh_r;
    if ((tid & 31) == 0) { rs[tid >> 5] = s; rq[tid >> 5] = sq; }
    __syncthreads();
    if (tid == 0) {
        float ts = 0.f, tq = 0.f;
        #pragma unroll
        for (int i = 0; i < 8; i++) { ts += rs[i]; tq += rq[i]; }
        float mu = ts * (1.0f / H_DIM);
        float var = tq * (1.0f / H_DIM) - mu * mu;
        sh_mu = mu;
        sh_r = rsqrtf(var + 1e-5f);
    }
    __syncthreads();
    float mu = sh_mu, r = sh_r;
    float4 w4 = ((const float4*)w)[tid];
    float4 b4 = ((const float4*)b)[tid];
    float4 o4;
    o4.x = (xv.x - mu) * r * w4.x + b4.x;
    o4.y = (xv.y - mu) * r * w4.y + b4.y;
    o4.z = (xv.z - mu) * r * w4.z + b4.z;
    o4.w = (xv.w - mu) * r * w4.w + b4.w;
    float* outp = (MODE == 0) ? g_hn : g_hn2;
    ((float4*)(outp + (size_t)row * H_DIM))[tid] = o4;
}

// ---------------- NT GEMM via tf32 tensor cores ----------------
template <int MODE>
__global__ __launch_bounds__(256, 2) void gemm_nt_tc(const float* __restrict__ Bw,
                                                     const float* __restrict__ bias,
                                                     const float* __restrict__ resid) {
    constexpr int N = (MODE == 0) ? H3 : H_DIM;
    constexpr int K = H_DIM;
    constexpr int NCH = K / 16;
    const float* A = (MODE == 0) ? g_hn : g_attn;
    float* C = (MODE == 0) ? g_qkv : g_x1;

    __shared__ float As[2][128][20];
    __shared__ float Bs[2][128][20];

    const int m0 = blockIdx.y * 128;
    const int n0 = blockIdx.x * 128;
    const int tid = threadIdx.x;
    const int lane = tid & 31;
    const int wid = tid >> 5;
    const int wm = (wid >> 2) * 64;
    const int wn = (wid & 3) * 32;
    const int g = lane >> 2;
    const int t = lane & 3;

    const int lr = tid >> 2;
    const int lk = (tid & 3) * 4;
    const float* Ap0 = A + (size_t)(m0 + lr) * K + lk;
    const float* Ap1 = A + (size_t)(m0 + lr + 64) * K + lk;
    const float* Bp0 = Bw + (size_t)(n0 + lr) * K + lk;
    const float* Bp1 = Bw + (size_t)(n0 + lr + 64) * K + lk;

    float acc[4][4][4];
    #pragma unroll
    for (int i = 0; i < 4; i++)
        #pragma unroll
        for (int j = 0; j < 4; j++)
            #pragma unroll
            for (int r = 0; r < 4; r++) acc[i][j][r] = 0.f;

    {
        cp16(sof(&As[0][lr][lk]), Ap0);
        cp16(sof(&As[0][lr + 64][lk]), Ap1);
        cp16(sof(&Bs[0][lr][lk]), Bp0);
        cp16(sof(&Bs[0][lr + 64][lk]), Bp1);
        cp_commit();
    }

    for (int c = 0; c < NCH; c++) {
        __syncthreads();
        if (c + 1 < NCH) {
            int s = (c + 1) & 1;
            int k0 = (c + 1) * 16;
            cp16(sof(&As[s][lr][lk]), Ap0 + k0);
            cp16(sof(&As[s][lr + 64][lk]), Ap1 + k0);
            cp16(sof(&Bs[s][lr][lk]), Bp0 + k0);
            cp16(sof(&Bs[s][lr + 64][lk]), Bp1 + k0);
            cp_commit();
            cp_wait<1>();
        } else {
            cp_wait<0>();
        }
        __syncthreads();
        const int s = c & 1;
        #pragma unroll
        for (int kk = 0; kk < 16; kk += 8) {
            uint32_t af[4][4], bf[4][2];
            #pragma unroll
            for (int i = 0; i < 4; i++) {
                int r = wm + i * 16 + g;
                af[i][0] = f2tf(As[s][r][kk + t]);
                af[i][1] = f2tf(As[s][r + 8][kk + t]);
                af[i][2] = f2tf(As[s][r][kk + t + 4]);
                af[i][3] = f2tf(As[s][r + 8][kk + t + 4]);
            }
            #pragma unroll
            for (int j = 0; j < 4; j++) {
                int n = wn + j * 8 + g;
                bf[j][0] = f2tf(Bs[s][n][kk + t]);
                bf[j][1] = f2tf(Bs[s][n][kk + t + 4]);
            }
            #pragma unroll
            for (int i = 0; i < 4; i++)
                #pragma unroll
                for (int j = 0; j < 4; j++)
                    mma_tf32(acc[i][j], af[i], bf[j]);
        }
    }

    #pragma unroll
    for (int i = 0; i < 4; i++) {
        int r0 = m0 + wm + i * 16 + g;
        #pragma unroll
        for (int j = 0; j < 4; j++) {
            int col = n0 + wn + j * 8 + 2 * t;
            float bx = bias[col], by = bias[col + 1];
            float2 v0, v1;
            v0.x = acc[i][j][0] + bx; v0.y = acc[i][j][1] + by;
            v1.x = acc[i][j][2] + bx; v1.y = acc[i][j][3] + by;
            if (MODE == 1) {
                float2 ra = *(const float2*)(resid + (size_t)r0 * N + col);
                float2 rb = *(const float2*)(resid + (size_t)(r0 + 8) * N + col);
                v0.x += ra.x; v0.y += ra.y;
                v1.x += rb.x; v1.y += rb.y;
            }
            *(float2*)(C + (size_t)r0 * N + col) = v0;
            *(float2*)(C + (size_t)(r0 + 8) * N + col) = v1;
        }
    }
}

// ---------------- Tensor-core flash attention (tf32, rna) ----------------
__global__ __launch_bounds__(128) void attn_tc() {
    const int head = blockIdx.y;
    const int q0 = blockIdx.x * 64;

    __shared__ float Qs[64][76];
    __shared__ float Ks[32][76];
    __shared__ float Vs[64][36];   // transposed: [d][key]
    __shared__ float Ps[64][36];   // probs, warp-private rows

    const int tid = threadIdx.x;
    const int lane = tid & 31;
    const int wid = tid >> 5;
    const int wm = wid * 16;
    const int g = lane >> 2;
    const int t = lane & 3;

    #pragma unroll
    for (int p = 0; p < 8; p++) {
        int flat = (p * 128 + tid) * 4;
        int r = flat >> 6, c = flat & 63;
        float4 v = *(const float4*)(g_qkv + (size_t)(q0 + r) * H3 + head * HD + c);
        Qs[r][c] = v.x * 0.125f; Qs[r][c + 1] = v.y * 0.125f;
        Qs[r][c + 2] = v.z * 0.125f; Qs[r][c + 3] = v.w * 0.125f;
    }

    float mrow[2] = {-1e30f, -1e30f};
    float lrow[2] = {0.f, 0.f};
    float oacc[8][4];
    #pragma unroll
    for (int j = 0; j < 8; j++)
        #pragma unroll
        for (int r = 0; r < 4; r++) oacc[j][r] = 0.f;

    const int row_g  = q0 + wm + g;
    const int row_g8 = row_g + 8;
    const int kend = q0 + 64;

    for (int k0 = 0; k0 < kend; k0 += 32) {
        __syncthreads();
        #pragma unroll
        for (int p = 0; p < 4; p++) {
            int flat = (p * 128 + tid) * 4;
            int r = flat >> 6, c = flat & 63;
            const float* base = g_qkv + (size_t)(k0 + r) * H3 + head * HD + c;
            float4 kv = *(const float4*)(base + H_DIM);
            float4 vv = *(const float4*)(base + 2 * H_DIM);
            Ks[r][c] = kv.x; Ks[r][c + 1] = kv.y; Ks[r][c + 2] = kv.z; Ks[r][c + 3] = kv.w;
            Vs[c][r] = vv.x; Vs[c + 1][r] = vv.y; Vs[c + 2][r] = vv.z; Vs[c + 3][r] = vv.w;
        }
        __syncthreads();

        float sacc[4][4];
        #pragma unroll
        for (int j = 0; j < 4; j++)
            #pragma unroll
            for (int r = 0; r < 4; r++) sacc[j][r] = 0.f;

        #pragma unroll
        for (int kk = 0; kk < 64; kk += 8) {
            uint32_t aq[4];
            aq[0] = f2tf(Qs[wm + g][kk + t]);
            aq[1] = f2tf(Qs[wm + g + 8][kk + t]);
            aq[2] = f2tf(Qs[wm + g][kk + t + 4]);
            aq[3] = f2tf(Qs[wm + g + 8][kk + t + 4]);
            #pragma unroll
            for (int j = 0; j < 4; j++) {
                uint32_t bk[2];
                bk[0] = f2tf(Ks[j * 8 + g][kk + t]);
                bk[1] = f2tf(Ks[j * 8 + g][kk + t + 4]);
                mma_tf32(sacc[j], aq, bk);
            }
        }

        float mx0 = -1e30f, mx1 = -1e30f;
        #pragma unroll
        for (int j = 0; j < 4; j++) {
            int c0 = k0 + j * 8 + 2 * t;
            if (c0 > row_g)      sacc[j][0] = -1e30f;
            if (c0 + 1 > row_g)  sacc[j][1] = -1e30f;
            if (c0 > row_g8)     sacc[j][2] = -1e30f;
            if (c0 + 1 > row_g8) sacc[j][3] = -1e30f;
            mx0 = fmaxf(mx0, fmaxf(sacc[j][0], sacc[j][1]));
            mx1 = fmaxf(mx1, fmaxf(sacc[j][2], sacc[j][3]));
        }
        #pragma unroll
        for (int o = 1; o <= 2; o <<= 1) {
            mx0 = fmaxf(mx0, __shfl_xor_sync(0xffffffffu, mx0, o));
            mx1 = fmaxf(mx1, __shfl_xor_sync(0xffffffffu, mx1, o));
        }
        float mn0 = fmaxf(mrow[0], mx0);
        float mn1 = fmaxf(mrow[1], mx1);
        float cor0 = __expf(mrow[0] - mn0);
        float cor1 = __expf(mrow[1] - mn1);
        mrow[0] = mn0; mrow[1] = mn1;

        float ls0 = 0.f, ls1 = 0.f;
        #pragma unroll
        for (int j = 0; j < 4; j++) {
            float p0 = __expf(sacc[j][0] - mn0);
            float p1 = __expf(sacc[j][1] - mn0);
            float p2 = __expf(sacc[j][2] - mn1);
            float p3 = __expf(sacc[j][3] - mn1);
            ls0 += p0 + p1; ls1 += p2 + p3;
            int c0 = j * 8 + 2 * t;
            *(float2*)&Ps[wm + g][c0]     = make_float2(p0, p1);
            *(float2*)&Ps[wm + g + 8][c0] = make_float2(p2, p3);
        }
        lrow[0] = lrow[0] * cor0 + ls0;
        lrow[1] = lrow[1] * cor1 + ls1;
        #pragma unroll
        for (int j = 0; j < 8; j++) {
            oacc[j][0] *= cor0; oacc[j][1] *= cor0;
            oacc[j][2] *= cor1; oacc[j][3] *= cor1;
        }
        __syncwarp();

        #pragma unroll
        for (int kk = 0; kk < 32; kk += 8) {
            uint32_t ap[4];
            ap[0] = f2tf(Ps[wm + g][kk + t]);
            ap[1] = f2tf(Ps[wm + g + 8][kk + t]);
            ap[2] = f2tf(Ps[wm + g][kk + t + 4]);
            ap[3] = f2tf(Ps[wm + g + 8][kk + t + 4]);
            #pragma unroll
            for (int j = 0; j < 8; j++) {
                uint32_t bv[2];
                bv[0] = f2tf(Vs[j * 8 + g][kk + t]);
                bv[1] = f2tf(Vs[j * 8 + g][kk + t + 4]);
                mma_tf32(oacc[j], ap, bv);
            }
        }
    }

    #pragma unroll
    for (int o = 1; o <= 2; o <<= 1) {
        lrow[0] += __shfl_xor_sync(0xffffffffu, lrow[0], o);
        lrow[1] += __shfl_xor_sync(0xffffffffu, lrow[1], o);
    }
    float inv0 = 1.f / lrow[0];
    float inv1 = 1.f / lrow[1];

    float* o0 = g_attn + (size_t)(q0 + wm + g) * H_DIM + head * HD;
    float* o1 = g_attn + (size_t)(q0 + wm + g + 8) * H_DIM + head * HD;
    #pragma unroll
    for (int j = 0; j < 8; j++) {
        int c = j * 8 + 2 * t;
        *(float2*)(o0 + c) = make_float2(oacc[j][0] * inv0, oacc[j][1] * inv0);
        *(float2*)(o1 + c) = make_float2(oacc[j][2] * inv1, oacc[j][3] * inv1);
    }
}

// ---------------- Router ----------------
__global__ __launch_bounds__(128) void router_kernel(const float* __restrict__ rw) {
    const int t = blockIdx.x;
    const int tid = threadIdx.x;
    float accs[NE];
    #pragma unroll
    for (int e = 0; e < NE; e++) accs[e] = 0.f;
    const float* xr = g_hn2 + (size_t)t * H_DIM;
    for (int j = tid; j < H_DIM; j += 128) {
        float xv = xr[j];
        #pragma unroll
        for (int e = 0; e < NE; e++) accs[e] += xv * rw[e * H_DIM + j];
    }
    #pragma unroll
    for (int e = 0; e < NE; e++) {
        #pragma unroll
        for (int o = 16; o; o >>= 1) accs[e] += __shfl_xor_sync(0xffffffffu, accs[e], o);
    }
    __shared__ float wred[NE][4];
    if ((tid & 31) == 0) {
        #pragma unroll
        for (int e = 0; e < NE; e++) wred[e][tid >> 5] = accs[e];
    }
    __syncthreads();
    if (tid == 0) {
        float lg[NE];
        float mx = -1e30f;
        #pragma unroll
        for (int e = 0; e < NE; e++) {
            lg[e] = wred[e][0] + wred[e][1] + wred[e][2] + wred[e][3];
            mx = fmaxf(mx, lg[e]);
        }
        float p[NE], sum = 0.f;
        #pragma unroll
        for (int e = 0; e < NE; e++) { p[e] = expf(lg[e] - mx); sum += p[e]; }
        float inv = 1.f / sum;
        #pragma unroll
        for (int e = 0; e < NE; e++) p[e] *= inv;
        int i0 = 0;
        #pragma unroll
        for (int e = 1; e < NE; e++) if (lg[e] > lg[i0]) i0 = e;
        int i1 = (i0 == 0) ? 1 : 0;
        #pragma unroll
        for (int e = 0; e < NE; e++) if (e != i0 && lg[e] > lg[i1]) i1 = e;
        g_expert[t * 2 + 0] = i0; g_gate[t * 2 + 0] = p[i0];
        g_expert[t * 2 + 1] = i1; g_gate[t * 2 + 1] = p[i1];
        atomicAdd(&g_counts[i0], 1);
        atomicAdd(&g_counts[i1], 1);
    }
}

__global__ void zero_kernel() {
    int i = threadIdx.x;
    if (i < NE) g_counts[i] = 0;
}

__global__ void scan_kernel() {
    if (threadIdx.x == 0) {
        int o = 0;
        for (int e = 0; e < NE; e++) { g_offsets[e] = o; o += g_counts[e]; g_cursor[e] = 0; }
    }
}

__global__ void fill_kernel() {
    int t = blockIdx.x * blockDim.x + threadIdx.x;
    if (t >= S_LEN) return;
    #pragma unroll
    for (int k = 0; k < TOPK; k++) {
        int e = g_expert[t * 2 + k];
        int pos = g_offsets[e] + atomicAdd(&g_cursor[e], 1);
        g_rowtok[pos] = t;
        g_slot[t * 2 + k] = pos;
    }
}

// ---------------- Grouped MoE GEMM (NN) via tf32 tensor cores ----------------
template <int STAGE>
__global__ __launch_bounds__(256, 2) void moe_gemm_tc(const float* __restrict__ Bsrc) {
    const int e = blockIdx.z;
    const int Me = g_counts[e];
    const int m0 = blockIdx.y * 128;
    if (m0 >= Me) return;
    const int off = g_offsets[e];
    constexpr int Kd = (STAGE == 1) ? H_DIM : FF;
    constexpr int Nn = (STAGE == 1) ? FF : H_DIM;
    constexpr int NCH = Kd / 16;
    const float* B = Bsrc + (size_t)e * Kd * Nn;
    const int n0 = blockIdx.x * 128;

    __shared__ float As[2][128][20];
    __shared__ float Bs[2][16][136];

    const int tid = threadIdx.x;
    const int lane = tid & 31;
    const int wid = tid >> 5;
    const int wm = (wid >> 2) * 64;
    const int wn = (wid & 3) * 32;
    const int g = lane >> 2;
    const int t = lane & 3;

    const int lr = tid >> 2;
    const int lk = (tid & 3) * 4;
    int mra = m0 + lr;       if (mra > Me - 1) mra = Me - 1;
    int mrb = m0 + lr + 64;  if (mrb > Me - 1) mrb = Me - 1;
    const float* Ap0;
    const float* Ap1;
    if (STAGE == 1) {
        Ap0 = g_hn2 + (size_t)g_rowtok[off + mra] * H_DIM + lk;
        Ap1 = g_hn2 + (size_t)g_rowtok[off + mrb] * H_DIM + lk;
    } else {
        Ap0 = g_hmid + (size_t)(off + mra) * FF + lk;
        Ap1 = g_hmid + (size_t)(off + mrb) * FF + lk;
    }
    const int bk0 = tid >> 5;
    const int bnc = (tid & 31) * 4;
    const float* Bp0 = B + (size_t)bk0 * Nn + n0 + bnc;
    const float* Bp1 = B + (size_t)(bk0 + 8) * Nn + n0 + bnc;

    float acc[4][4][4];
    #pragma unroll
    for (int i = 0; i < 4; i++)
        #pragma unroll
        for (int j = 0; j < 4; j++)
            #pragma unroll
            for (int r = 0; r < 4; r++) acc[i][j][r] = 0.f;

    {
        cp16(sof(&As[0][lr][lk]), Ap0);
        cp16(sof(&As[0][lr + 64][lk]), Ap1);
        cp16(sof(&Bs[0][bk0][bnc]), Bp0);
        cp16(sof(&Bs[0][bk0 + 8][bnc]), Bp1);
        cp_commit();
    }

    for (int c = 0; c < NCH; c++) {
        __syncthreads();
        if (c + 1 < NCH) {
            int s = (c + 1) & 1;
            int k0 = (c + 1) * 16;
            cp16(sof(&As[s][lr][lk]), Ap0 + k0);
            cp16(sof(&As[s][lr + 64][lk]), Ap1 + k0);
            cp16(sof(&Bs[s][bk0][bnc]), Bp0 + (size_t)k0 * Nn);
            cp16(sof(&Bs[s][bk0 + 8][bnc]), Bp1 + (size_t)k0 * Nn);
            cp_commit();
            cp_wait<1>();
        } else {
            cp_wait<0>();
        }
        __syncthreads();
        const int s = c & 1;
        #pragma unroll
        for (int kk = 0; kk < 16; kk += 8) {
            uint32_t af[4][4], bf[4][2];
            #pragma unroll
            for (int i = 0; i < 4; i++) {
                int r = wm + i * 16 + g;
                af[i][0] = f2tf(As[s][r][kk + t]);
                af[i][1] = f2tf(As[s][r + 8][kk + t]);
                af[i][2] = f2tf(As[s][r][kk + t + 4]);
                af[i][3] = f2tf(As[s][r + 8][kk + t + 4]);
            }
            #pragma unroll
            for (int j = 0; j < 4; j++) {
                int n = wn + j * 8 + g;
                bf[j][0] = f2tf(Bs[s][kk + t][n]);
                bf[j][1] = f2tf(Bs[s][kk + t + 4][n]);
            }
            #pragma unroll
            for (int i = 0; i < 4; i++)
                #pragma unroll
                for (int j = 0; j < 4; j++)
                    mma_tf32(acc[i][j], af[i], bf[j]);
        }
    }

    #pragma unroll
    for (int i = 0; i < 4; i++) {
        int rloc0 = wm + i * 16 + g;
        #pragma unroll
        for (int j = 0; j < 4; j++) {
            int col = n0 + wn + j * 8 + 2 * t;
            #pragma unroll
            for (int half = 0; half < 2; half++) {
                int mloc = rloc0 + half * 8;
                int m = m0 + mloc;
                if (m >= Me) continue;
                float2 v;
                v.x = acc[i][j][half * 2 + 0];
                v.y = acc[i][j][half * 2 + 1];
                if (STAGE == 1) {
                    v.x = 0.5f * v.x * (1.f + erff(v.x * 0.70710678118654752f));
                    v.y = 0.5f * v.y * (1.f + erff(v.y * 0.70710678118654752f));
                    *(float2*)(g_hmid + (size_t)(off + m) * FF + col) = v;
                } else {
                    *(float2*)(g_yslot + (size_t)(off + m) * H_DIM + col) = v;
                }
            }
        }
    }
}

// ---------------- Combine ----------------
__global__ __launch_bounds__(256) void combine_kernel(float* __restrict__ out) {
    const int t = blockIdx.x;
    const int s0 = g_slot[t * 2 + 0];
    const int s1 = g_slot[t * 2 + 1];
    const float g0 = g_gate[t * 2 + 0];
    const float g1 = g_gate[t * 2 + 1];
    const float4* y0 = (const float4*)(g_yslot + (size_t)s0 * H_DIM);
    const float4* y1 = (const float4*)(g_yslot + (size_t)s1 * H_DIM);
    const float4* x1 = (const float4*)(g_x1 + (size_t)t * H_DIM);
    float4* o = (float4*)(out + (size_t)t * H_DIM);
    int i = threadIdx.x;
    float4 a = x1[i], b = y0[i], c = y1[i];
    float4 r;
    r.x = a.x + g0 * b.x + g1 * c.x;
    r.y = a.y + g0 * b.y + g1 * c.y;
    r.z = a.z + g0 * b.z + g1 * c.z;
    r.w = a.w + g0 * b.w + g1 * c.w;
    o[i] = r;
}

// ---------------- launch ----------------
extern "C" void kernel_launch(void* const* d_in, const int* in_sizes, int n_in,
                              void* d_out, int out_size) {
    (void)in_sizes; (void)n_in; (void)out_size;
    const float* x          = (const float*)d_in[0];
    const float* ln1_w      = (const float*)d_in[1];
    const float* ln1_b      = (const float*)d_in[2];
    const float* in_proj_w  = (const float*)d_in[3];
    const float* in_proj_b  = (const float*)d_in[4];
    const float* out_proj_w = (const float*)d_in[5];
    const float* out_proj_b = (const float*)d_in[6];
    const float* ln2_w      = (const float*)d_in[7];
    const float* ln2_b      = (const float*)d_in[8];
    const float* router_w   = (const float*)d_in[9];
    const float* w1         = (const float*)d_in[10];
    const float* w2         = (const float*)d_in[11];
    float* out = (float*)d_out;

    ln_kernel<0><<<S_LEN, 256>>>(x, ln1_w, ln1_b);
    gemm_nt_tc<0><<<dim3(H3 / 128, S_LEN / 128), 256>>>(in_proj_w, in_proj_b, nullptr);
    attn_tc<<<dim3(S_LEN / 64, NH), 128>>>();
    gemm_nt_tc<1><<<dim3(H_DIM / 128, S_LEN / 128), 256>>>(out_proj_w, out_proj_b, x);
    ln_kernel<1><<<S_LEN, 256>>>(nullptr, ln2_w, ln2_b);
    zero_kernel<<<1, 32>>>();
    router_kernel<<<S_LEN, 128>>>(router_w);
    scan_kernel<<<1, 32>>>();
    fill_kernel<<<S_LEN / 256, 256>>>();
    moe_gemm_tc<1><<<dim3(FF / 128, S_LEN / 128, NE), 256>>>(w1);
    moe_gemm_tc<2><<<dim3(H_DIM / 128, S_LEN / 128, NE), 256>>>(w2);
    combine_kernel<<<S_LEN, 256>>>(out);
}

// round 5
// speedup vs baseline: 3.9797x; 1.0737x over previous
#include <cuda_runtime.h>
#include <cstdint>
#include <math.h>

#define S_LEN 2048
#define H_DIM 1024
#define NH 16
#define HD 64
#define H3 3072
#define NE 8
#define TOPK 2
#define FF 2048
#define NSLOT (S_LEN * TOPK)

// ---------------- scratch ----------------
__device__ float g_hn[S_LEN * H_DIM];      // tf32-rounded LN1 out
__device__ float g_qkv[S_LEN * H3];        // tf32-rounded qkv
__device__ float g_attn[S_LEN * H_DIM];    // tf32-rounded attention out
__device__ float g_x1[S_LEN * H_DIM];      // FULL precision residual
__device__ float g_hn2[S_LEN * H_DIM];     // FULL precision (router)
__device__ float g_hn2t[S_LEN * H_DIM];    // tf32-rounded (MoE A)
__device__ float g_ipw[H3 * H_DIM];        // tf32-rounded in_proj_w
__device__ float g_opw[H_DIM * H_DIM];     // tf32-rounded out_proj_w
__device__ float g_gate[S_LEN * TOPK];
__device__ int   g_expert[S_LEN * TOPK];
__device__ int   g_slot[S_LEN * TOPK];
__device__ int   g_rowtok[NSLOT];
__device__ int   g_counts[NE];
__device__ int   g_offsets[NE];
__device__ int   g_cursor[NE];
__device__ float g_hmid[(size_t)NSLOT * FF];     // tf32-rounded GELU out
__device__ float g_yslot[(size_t)NSLOT * H_DIM]; // full precision

// ---------------- PTX helpers ----------------
__device__ __forceinline__ uint32_t sof(const void* p) {
    return (uint32_t)__cvta_generic_to_shared(p);
}
__device__ __forceinline__ void cp16(uint32_t s, const void* g) {
    asm volatile("cp.async.cg.shared.global [%0], [%1], 16;\n" :: "r"(s), "l"(g));
}
__device__ __forceinline__ void cp_commit() { asm volatile("cp.async.commit_group;\n"); }
template <int N>
__device__ __forceinline__ void cp_wait() { asm volatile("cp.async.wait_group %0;\n" :: "n"(N)); }

__device__ __forceinline__ uint32_t f2tf(float x) {
    uint32_t r;
    asm("cvt.rna.tf32.f32 %0, %1;" : "=r"(r) : "f"(x));
    return r;
}
__device__ __forceinline__ float rtf(float x) { return __uint_as_float(f2tf(x)); }
__device__ __forceinline__ uint32_t fbits(float x) { return __float_as_uint(x); }

__device__ __forceinline__ void mma_tf32(float* c, const uint32_t* a, const uint32_t* b) {
    asm volatile(
        "mma.sync.aligned.m16n8k8.row.col.f32.tf32.tf32.f32 "
        "{%0,%1,%2,%3}, {%4,%5,%6,%7}, {%8,%9}, {%0,%1,%2,%3};\n"
        : "+f"(c[0]), "+f"(c[1]), "+f"(c[2]), "+f"(c[3])
        : "r"(a[0]), "r"(a[1]), "r"(a[2]), "r"(a[3]), "r"(b[0]), "r"(b[1]));
}
__device__ __forceinline__ void ldsm_x4(uint32_t a, uint32_t* r) {
    asm volatile("ldmatrix.sync.aligned.m8n8.x4.shared.b16 {%0,%1,%2,%3}, [%4];"
                 : "=r"(r[0]), "=r"(r[1]), "=r"(r[2]), "=r"(r[3]) : "r"(a));
}
__device__ __forceinline__ void ldsm_x2(uint32_t a, uint32_t* r) {
    asm volatile("ldmatrix.sync.aligned.m8n8.x2.shared.b16 {%0,%1}, [%2];"
                 : "=r"(r[0]), "=r"(r[1]) : "r"(a));
}

// ---------------- weight tf32-rounding copy ----------------
__global__ __launch_bounds__(256) void cvt_w_kernel(const float4* __restrict__ src,
                                                    float4* __restrict__ dst, int n4) {
    int i = blockIdx.x * blockDim.x + threadIdx.x;
    if (i >= n4) return;
    float4 v = src[i];
    v.x = rtf(v.x); v.y = rtf(v.y); v.z = rtf(v.z); v.w = rtf(v.w);
    dst[i] = v;
}

// ---------------- LayerNorm ----------------
// MODE 0: in = xp, out = g_hn (rounded). MODE 1: in = g_x1, out = g_hn2 (full) + g_hn2t (rounded)
template <int MODE>
__global__ __launch_bounds__(256) void ln_kernel(const float* __restrict__ xp,
                                                 const float* __restrict__ w,
                                                 const float* __restrict__ b) {
    const int row = blockIdx.x;
    const int tid = threadIdx.x;
    const float* xin = (MODE == 0) ? xp : g_x1;
    const float* xr = xin + (size_t)row * H_DIM;

    float4 xv = ((const float4*)xr)[tid];
    float s  = xv.x + xv.y + xv.z + xv.w;
    float sq = xv.x * xv.x + xv.y * xv.y + xv.z * xv.z + xv.w * xv.w;
    #pragma unroll
    for (int o = 16; o; o >>= 1) {
        s  += __shfl_xor_sync(0xffffffffu, s, o);
        sq += __shfl_xor_sync(0xffffffffu, sq, o);
    }
    __shared__ float rs[8], rq[8];
    __shared__ float sh_mu, sh_r;
    if ((tid & 31) == 0) { rs[tid >> 5] = s; rq[tid >> 5] = sq; }
    __syncthreads();
    if (tid == 0) {
        float ts = 0.f, tq = 0.f;
        #pragma unroll
        for (int i = 0; i < 8; i++) { ts += rs[i]; tq += rq[i]; }
        float mu = ts * (1.0f / H_DIM);
        float var = tq * (1.0f / H_DIM) - mu * mu;
        sh_mu = mu;
        sh_r = rsqrtf(var + 1e-5f);
    }
    __syncthreads();
    float mu = sh_mu, r = sh_r;
    float4 w4 = ((const float4*)w)[tid];
    float4 b4 = ((const float4*)b)[tid];
    float4 o4;
    o4.x = (xv.x - mu) * r * w4.x + b4.x;
    o4.y = (xv.y - mu) * r * w4.y + b4.y;
    o4.z = (xv.z - mu) * r * w4.z + b4.z;
    o4.w = (xv.w - mu) * r * w4.w + b4.w;
    float4 o4r;
    o4r.x = rtf(o4.x); o4r.y = rtf(o4.y); o4r.z = rtf(o4.z); o4r.w = rtf(o4.w);
    if (MODE == 0) {
        ((float4*)(g_hn + (size_t)row * H_DIM))[tid] = o4r;
    } else {
        ((float4*)(g_hn2 + (size_t)row * H_DIM))[tid] = o4;
        ((float4*)(g_hn2t + (size_t)row * H_DIM))[tid] = o4r;
    }
}

// ---------------- NT GEMM via tf32 tensor cores, 4-stage, ldmatrix ----------------
// MODE 0: A=g_hn (rounded), B=g_ipw (rounded), C=g_qkv (store rounded)
// MODE 1: A=g_attn (rounded), B=g_opw (rounded), C=g_x1 = acc + bias + resid (full)
#define GEMM_STAGES 4
#define GEMM_ASZ (128 * 20)
#define GEMM_STGF (2 * GEMM_ASZ)
#define GEMM_SMEM (GEMM_STAGES * GEMM_STGF * 4)

template <int MODE>
__global__ __launch_bounds__(256, 2) void gemm_nt_tc(const float* __restrict__ bias,
                                                     const float* __restrict__ resid) {
    constexpr int N = (MODE == 0) ? H3 : H_DIM;
    constexpr int K = H_DIM;
    constexpr int NCH = K / 16;
    const float* A = (MODE == 0) ? g_hn : g_attn;
    const float* Bw = (MODE == 0) ? g_ipw : g_opw;
    float* C = (MODE == 0) ? g_qkv : g_x1;

    extern __shared__ float smf[];
    const uint32_t sm0 = sof(smf);

    const int m0 = blockIdx.y * 128;
    const int n0 = blockIdx.x * 128;
    const int tid = threadIdx.x;
    const int lane = tid & 31;
    const int wid = tid >> 5;
    const int wm = (wid >> 2) * 64;
    const int wn = (wid & 3) * 32;
    const int g = lane >> 2;
    const int t = lane & 3;

    const int lr = tid >> 2;
    const int lk = (tid & 3) * 4;
    const float* Ap0 = A + (size_t)(m0 + lr) * K + lk;
    const float* Ap1 = A + (size_t)(m0 + lr + 64) * K + lk;
    const float* Bp0 = Bw + (size_t)(n0 + lr) * K + lk;
    const float* Bp1 = Bw + (size_t)(n0 + lr + 64) * K + lk;

    const uint32_t a_row = lane & 15;
    const uint32_t a_hi = (lane & 16) ? 16u : 0u;
    const uint32_t b_row = lane & 7;
    const uint32_t b_hi = (lane & 8) ? 16u : 0u;

    float acc[4][4][4];
    #pragma unroll
    for (int i = 0; i < 4; i++)
        #pragma unroll
        for (int j = 0; j < 4; j++)
            #pragma unroll
            for (int r = 0; r < 4; r++) acc[i][j][r] = 0.f;

    #define GLD(slot, k0) do { \
        uint32_t ab = sm0 + (uint32_t)(slot) * (GEMM_STGF * 4); \
        cp16(ab + (lr * 20 + lk) * 4, Ap0 + (k0)); \
        cp16(ab + ((lr + 64) * 20 + lk) * 4, Ap1 + (k0)); \
        uint32_t bb = ab + GEMM_ASZ * 4; \
        cp16(bb + (lr * 20 + lk) * 4, Bp0 + (k0)); \
        cp16(bb + ((lr + 64) * 20 + lk) * 4, Bp1 + (k0)); \
        cp_commit(); } while (0)

    GLD(0, 0); GLD(1, 16); GLD(2, 32);

    for (int c = 0; c < NCH; c++) {
        cp_wait<GEMM_STAGES - 2>();
        __syncthreads();
        if (c + 3 < NCH) GLD((c + 3) & 3, (c + 3) * 16);
        const int s = c & 3;
        uint32_t abase = sm0 + (uint32_t)(s * GEMM_STGF + (wm + a_row) * 20) * 4 + a_hi;
        uint32_t bbase = sm0 + (uint32_t)(s * GEMM_STGF + GEMM_ASZ + (wn + b_row) * 20) * 4 + b_hi;
        #pragma unroll
        for (int kk2 = 0; kk2 < 2; kk2++) {
            const uint32_t kb = kk2 * 32;
            uint32_t af[4][4], bf[4][2];
            #pragma unroll
            for (int i = 0; i < 4; i++) ldsm_x4(abase + i * 1280 + kb, af[i]);
            #pragma unroll
            for (int j = 0; j < 4; j++) ldsm_x2(bbase + j * 640 + kb, bf[j]);
            #pragma unroll
            for (int i = 0; i < 4; i++)
                #pragma unroll
                for (int j = 0; j < 4; j++)
                    mma_tf32(acc[i][j], af[i], bf[j]);
        }
    }
    #undef GLD

    #pragma unroll
    for (int i = 0; i < 4; i++) {
        int r0 = m0 + wm + i * 16 + g;
        #pragma unroll
        for (int j = 0; j < 4; j++) {
            int col = n0 + wn + j * 8 + 2 * t;
            float bx = bias[col], by = bias[col + 1];
            float2 v0, v1;
            v0.x = acc[i][j][0] + bx; v0.y = acc[i][j][1] + by;
            v1.x = acc[i][j][2] + bx; v1.y = acc[i][j][3] + by;
            if (MODE == 1) {
                float2 ra = *(const float2*)(resid + (size_t)r0 * N + col);
                float2 rb = *(const float2*)(resid + (size_t)(r0 + 8) * N + col);
                v0.x += ra.x; v0.y += ra.y;
                v1.x += rb.x; v1.y += rb.y;
            } else {
                v0.x = rtf(v0.x); v0.y = rtf(v0.y);
                v1.x = rtf(v1.x); v1.y = rtf(v1.y);
            }
            *(float2*)(C + (size_t)r0 * N + col) = v0;
            *(float2*)(C + (size_t)(r0 + 8) * N + col) = v1;
        }
    }
}

// ---------------- Tensor-core flash attention (inputs pre-rounded tf32) ----------------
__global__ __launch_bounds__(128) void attn_tc() {
    const int head = blockIdx.y;
    const int q0 = blockIdx.x * 64;

    __shared__ float Qs[64][76];
    __shared__ float Ks[32][76];
    __shared__ float Vs[64][36];   // transposed: [d][key]
    __shared__ float Ps[64][36];

    const int tid = threadIdx.x;
    const int lane = tid & 31;
    const int wid = tid >> 5;
    const int wm = wid * 16;
    const int g = lane >> 2;
    const int t = lane & 3;

    #pragma unroll
    for (int p = 0; p < 8; p++) {
        int flat = (p * 128 + tid) * 4;
        int r = flat >> 6, c = flat & 63;
        float4 v = *(const float4*)(g_qkv + (size_t)(q0 + r) * H3 + head * HD + c);
        Qs[r][c] = v.x * 0.125f; Qs[r][c + 1] = v.y * 0.125f;
        Qs[r][c + 2] = v.z * 0.125f; Qs[r][c + 3] = v.w * 0.125f;
    }

    float mrow[2] = {-1e30f, -1e30f};
    float lrow[2] = {0.f, 0.f};
    float oacc[8][4];
    #pragma unroll
    for (int j = 0; j < 8; j++)
        #pragma unroll
        for (int r = 0; r < 4; r++) oacc[j][r] = 0.f;

    const int row_g  = q0 + wm + g;
    const int row_g8 = row_g + 8;
    const int kend = q0 + 64;

    for (int k0 = 0; k0 < kend; k0 += 32) {
        __syncthreads();
        #pragma unroll
        for (int p = 0; p < 4; p++) {
            int flat = (p * 128 + tid) * 4;
            int r = flat >> 6, c = flat & 63;
            const float* base = g_qkv + (size_t)(k0 + r) * H3 + head * HD + c;
            float4 kv = *(const float4*)(base + H_DIM);
            float4 vv = *(const float4*)(base + 2 * H_DIM);
            Ks[r][c] = kv.x; Ks[r][c + 1] = kv.y; Ks[r][c + 2] = kv.z; Ks[r][c + 3] = kv.w;
            Vs[c][r] = vv.x; Vs[c + 1][r] = vv.y; Vs[c + 2][r] = vv.z; Vs[c + 3][r] = vv.w;
        }
        __syncthreads();

        float sacc[4][4];
        #pragma unroll
        for (int j = 0; j < 4; j++)
            #pragma unroll
            for (int r = 0; r < 4; r++) sacc[j][r] = 0.f;

        #pragma unroll
        for (int kk = 0; kk < 64; kk += 8) {
            uint32_t aq[4];
            aq[0] = fbits(Qs[wm + g][kk + t]);
            aq[1] = fbits(Qs[wm + g + 8][kk + t]);
            aq[2] = fbits(Qs[wm + g][kk + t + 4]);
            aq[3] = fbits(Qs[wm + g + 8][kk + t + 4]);
            #pragma unroll
            for (int j = 0; j < 4; j++) {
                uint32_t bk[2];
                bk[0] = fbits(Ks[j * 8 + g][kk + t]);
                bk[1] = fbits(Ks[j * 8 + g][kk + t + 4]);
                mma_tf32(sacc[j], aq, bk);
            }
        }

        float mx0 = -1e30f, mx1 = -1e30f;
        #pragma unroll
        for (int j = 0; j < 4; j++) {
            int c0 = k0 + j * 8 + 2 * t;
            if (c0 > row_g)      sacc[j][0] = -1e30f;
            if (c0 + 1 > row_g)  sacc[j][1] = -1e30f;
            if (c0 > row_g8)     sacc[j][2] = -1e30f;
            if (c0 + 1 > row_g8) sacc[j][3] = -1e30f;
            mx0 = fmaxf(mx0, fmaxf(sacc[j][0], sacc[j][1]));
            mx1 = fmaxf(mx1, fmaxf(sacc[j][2], sacc[j][3]));
        }
        #pragma unroll
        for (int o = 1; o <= 2; o <<= 1) {
            mx0 = fmaxf(mx0, __shfl_xor_sync(0xffffffffu, mx0, o));
            mx1 = fmaxf(mx1, __shfl_xor_sync(0xffffffffu, mx1, o));
        }
        float mn0 = fmaxf(mrow[0], mx0);
        float mn1 = fmaxf(mrow[1], mx1);
        float cor0 = __expf(mrow[0] - mn0);
        float cor1 = __expf(mrow[1] - mn1);
        mrow[0] = mn0; mrow[1] = mn1;

        float ls0 = 0.f, ls1 = 0.f;
        #pragma unroll
        for (int j = 0; j < 4; j++) {
            float p0 = __expf(sacc[j][0] - mn0);
            float p1 = __expf(sacc[j][1] - mn0);
            float p2 = __expf(sacc[j][2] - mn1);
            float p3 = __expf(sacc[j][3] - mn1);
            ls0 += p0 + p1; ls1 += p2 + p3;
            int c0 = j * 8 + 2 * t;
            *(float2*)&Ps[wm + g][c0]     = make_float2(__uint_as_float(f2tf(p0)), __uint_as_float(f2tf(p1)));
            *(float2*)&Ps[wm + g + 8][c0] = make_float2(__uint_as_float(f2tf(p2)), __uint_as_float(f2tf(p3)));
        }
        lrow[0] = lrow[0] * cor0 + ls0;
        lrow[1] = lrow[1] * cor1 + ls1;
        #pragma unroll
        for (int j = 0; j < 8; j++) {
            oacc[j][0] *= cor0; oacc[j][1] *= cor0;
            oacc[j][2] *= cor1; oacc[j][3] *= cor1;
        }
        __syncwarp();

        #pragma unroll
        for (int kk = 0; kk < 32; kk += 8) {
            uint32_t ap[4];
            ap[0] = fbits(Ps[wm + g][kk + t]);
            ap[1] = fbits(Ps[wm + g + 8][kk + t]);
            ap[2] = fbits(Ps[wm + g][kk + t + 4]);
            ap[3] = fbits(Ps[wm + g + 8][kk + t + 4]);
            #pragma unroll
            for (int j = 0; j < 8; j++) {
                uint32_t bv[2];
                bv[0] = fbits(Vs[j * 8 + g][kk + t]);
                bv[1] = fbits(Vs[j * 8 + g][kk + t + 4]);
                mma_tf32(oacc[j], ap, bv);
            }
        }
    }

    #pragma unroll
    for (int o = 1; o <= 2; o <<= 1) {
        lrow[0] += __shfl_xor_sync(0xffffffffu, lrow[0], o);
        lrow[1] += __shfl_xor_sync(0xffffffffu, lrow[1], o);
    }
    float inv0 = 1.f / lrow[0];
    float inv1 = 1.f / lrow[1];

    float* o0 = g_attn + (size_t)(q0 + wm + g) * H_DIM + head * HD;
    float* o1 = g_attn + (size_t)(q0 + wm + g + 8) * H_DIM + head * HD;
    #pragma unroll
    for (int j = 0; j < 8; j++) {
        int c = j * 8 + 2 * t;
        *(float2*)(o0 + c) = make_float2(rtf(oacc[j][0] * inv0), rtf(oacc[j][1] * inv0));
        *(float2*)(o1 + c) = make_float2(rtf(oacc[j][2] * inv1), rtf(oacc[j][3] * inv1));
    }
}

// ---------------- Router (full precision inputs) ----------------
__global__ __launch_bounds__(128) void router_kernel(const float* __restrict__ rw) {
    const int t = blockIdx.x;
    const int tid = threadIdx.x;
    float accs[NE];
    #pragma unroll
    for (int e = 0; e < NE; e++) accs[e] = 0.f;
    const float* xr = g_hn2 + (size_t)t * H_DIM;
    for (int j = tid; j < H_DIM; j += 128) {
        float xv = xr[j];
        #pragma unroll
        for (int e = 0; e < NE; e++) accs[e] += xv * rw[e * H_DIM + j];
    }
    #pragma unroll
    for (int e = 0; e < NE; e++) {
        #pragma unroll
        for (int o = 16; o; o >>= 1) accs[e] += __shfl_xor_sync(0xffffffffu, accs[e], o);
    }
    __shared__ float wred[NE][4];
    if ((tid & 31) == 0) {
        #pragma unroll
        for (int e = 0; e < NE; e++) wred[e][tid >> 5] = accs[e];
    }
    __syncthreads();
    if (tid == 0) {
        float lg[NE];
        float mx = -1e30f;
        #pragma unroll
        for (int e = 0; e < NE; e++) {
            lg[e] = wred[e][0] + wred[e][1] + wred[e][2] + wred[e][3];
            mx = fmaxf(mx, lg[e]);
        }
        float p[NE], sum = 0.f;
        #pragma unroll
        for (int e = 0; e < NE; e++) { p[e] = expf(lg[e] - mx); sum += p[e]; }
        float inv = 1.f / sum;
        #pragma unroll
        for (int e = 0; e < NE; e++) p[e] *= inv;
        int i0 = 0;
        #pragma unroll
        for (int e = 1; e < NE; e++) if (lg[e] > lg[i0]) i0 = e;
        int i1 = (i0 == 0) ? 1 : 0;
        #pragma unroll
        for (int e = 0; e < NE; e++) if (e != i0 && lg[e] > lg[i1]) i1 = e;
        g_expert[t * 2 + 0] = i0; g_gate[t * 2 + 0] = p[i0];
        g_expert[t * 2 + 1] = i1; g_gate[t * 2 + 1] = p[i1];
        atomicAdd(&g_counts[i0], 1);
        atomicAdd(&g_counts[i1], 1);
    }
}

__global__ void zero_kernel() {
    int i = threadIdx.x;
    if (i < NE) g_counts[i] = 0;
}

__global__ void scan_kernel() {
    if (threadIdx.x == 0) {
        int o = 0;
        for (int e = 0; e < NE; e++) { g_offsets[e] = o; o += g_counts[e]; g_cursor[e] = 0; }
    }
}

__global__ void fill_kernel() {
    int t = blockIdx.x * blockDim.x + threadIdx.x;
    if (t >= S_LEN) return;
    #pragma unroll
    for (int k = 0; k < TOPK; k++) {
        int e = g_expert[t * 2 + k];
        int pos = g_offsets[e] + atomicAdd(&g_cursor[e], 1);
        g_rowtok[pos] = t;
        g_slot[t * 2 + k] = pos;
    }
}

// ---------------- Grouped MoE GEMM (NN), 4-stage, ldmatrix A ----------------
#define MOE_STAGES 4
#define MOE_ASZ (128 * 20)
#define MOE_BSZ (16 * 136)
#define MOE_STGF (MOE_ASZ + MOE_BSZ)
#define MOE_SMEM (MOE_STAGES * MOE_STGF * 4)

template <int STAGE>
__global__ __launch_bounds__(256, 2) void moe_gemm_tc(const float* __restrict__ Bsrc) {
    const int e = blockIdx.z;
    const int Me = g_counts[e];
    const int m0 = blockIdx.y * 128;
    if (m0 >= Me) return;
    const int off = g_offsets[e];
    constexpr int Kd = (STAGE == 1) ? H_DIM : FF;
    constexpr int Nn = (STAGE == 1) ? FF : H_DIM;
    constexpr int NCH = Kd / 16;
    const float* B = Bsrc + (size_t)e * Kd * Nn;
    const int n0 = blockIdx.x * 128;

    extern __shared__ float smf[];
    const uint32_t sm0 = sof(smf);

    const int tid = threadIdx.x;
    const int lane = tid & 31;
    const int wid = tid >> 5;
    const int wm = (wid >> 2) * 64;
    const int wn = (wid & 3) * 32;
    const int g = lane >> 2;
    const int t = lane & 3;

    const int lr = tid >> 2;
    const int lk = (tid & 3) * 4;
    int mra = m0 + lr;       if (mra > Me - 1) mra = Me - 1;
    int mrb = m0 + lr + 64;  if (mrb > Me - 1) mrb = Me - 1;
    const float* Ap0;
    const float* Ap1;
    if (STAGE == 1) {
        Ap0 = g_hn2t + (size_t)g_rowtok[off + mra] * H_DIM + lk;
        Ap1 = g_hn2t + (size_t)g_rowtok[off + mrb] * H_DIM + lk;
    } else {
        Ap0 = g_hmid + (size_t)(off + mra) * FF + lk;
        Ap1 = g_hmid + (size_t)(off + mrb) * FF + lk;
    }
    const int bk0 = tid >> 5;
    const int bnc = (tid & 31) * 4;
    const float* Bp0 = B + (size_t)bk0 * Nn + n0 + bnc;
    const float* Bp1 = B + (size_t)(bk0 + 8) * Nn + n0 + bnc;

    const uint32_t a_row = lane & 15;
    const uint32_t a_hi = (lane & 16) ? 16u : 0u;

    float acc[4][4][4];
    #pragma unroll
    for (int i = 0; i < 4; i++)
        #pragma unroll
        for (int j = 0; j < 4; j++)
            #pragma unroll
            for (int r = 0; r < 4; r++) acc[i][j][r] = 0.f;

    #define MLD(slot, k0) do { \
        uint32_t ab = sm0 + (uint32_t)(slot) * (MOE_STGF * 4); \
        cp16(ab + (lr * 20 + lk) * 4, Ap0 + (k0)); \
        cp16(ab + ((lr + 64) * 20 + lk) * 4, Ap1 + (k0)); \
        uint32_t bb = ab + MOE_ASZ * 4; \
        cp16(bb + (bk0 * 136 + bnc) * 4, Bp0 + (size_t)(k0) * Nn); \
        cp16(bb + ((bk0 + 8) * 136 + bnc) * 4, Bp1 + (size_t)(k0) * Nn); \
        cp_commit(); } while (0)

    MLD(0, 0); MLD(1, 16); MLD(2, 32);

    for (int c = 0; c < NCH; c++) {
        cp_wait<MOE_STAGES - 2>();
        __syncthreads();
        if (c + 3 < NCH) MLD((c + 3) & 3, (c + 3) * 16);
        const int s = c & 3;
        uint32_t abase = sm0 + (uint32_t)(s * MOE_STGF + (wm + a_row) * 20) * 4 + a_hi;
        const float* bsf = smf + s * MOE_STGF + MOE_ASZ;
        #pragma unroll
        for (int kk2 = 0; kk2 < 2; kk2++) {
            const int kk = kk2 * 8;
            uint32_t af[4][4], bf[4][2];
            #pragma unroll
            for (int i = 0; i < 4; i++) ldsm_x4(abase + i * 1280 + kk2 * 32, af[i]);
            #pragma unroll
            for (int j = 0; j < 4; j++) {
                int n = wn + j * 8 + g;
                bf[j][0] = f2tf(bsf[(kk + t) * 136 + n]);
                bf[j][1] = f2tf(bsf[(kk + t + 4) * 136 + n]);
            }
            #pragma unroll
            for (int i = 0; i < 4; i++)
                #pragma unroll
                for (int j = 0; j < 4; j++)
                    mma_tf32(acc[i][j], af[i], bf[j]);
        }
    }
    #undef MLD

    #pragma unroll
    for (int i = 0; i < 4; i++) {
        int rloc0 = wm + i * 16 + g;
        #pragma unroll
        for (int j = 0; j < 4; j++) {
            int col = n0 + wn + j * 8 + 2 * t;
            #pragma unroll
            for (int half = 0; half < 2; half++) {
                int mloc = rloc0 + half * 8;
                int m = m0 + mloc;
                if (m >= Me) continue;
                float2 v;
                v.x = acc[i][j][half * 2 + 0];
                v.y = acc[i][j][half * 2 + 1];
                if (STAGE == 1) {
                    v.x = 0.5f * v.x * (1.f + erff(v.x * 0.70710678118654752f));
                    v.y = 0.5f * v.y * (1.f + erff(v.y * 0.70710678118654752f));
                    v.x = rtf(v.x); v.y = rtf(v.y);
                    *(float2*)(g_hmid + (size_t)(off + m) * FF + col) = v;
                } else {
                    *(float2*)(g_yslot + (size_t)(off + m) * H_DIM + col) = v;
                }
            }
        }
    }
}

// ---------------- Combine ----------------
__global__ __launch_bounds__(256) void combine_kernel(float* __restrict__ out) {
    const int t = blockIdx.x;
    const int s0 = g_slot[t * 2 + 0];
    const int s1 = g_slot[t * 2 + 1];
    const float g0 = g_gate[t * 2 + 0];
    const float g1 = g_gate[t * 2 + 1];
    const float4* y0 = (const float4*)(g_yslot + (size_t)s0 * H_DIM);
    const float4* y1 = (const float4*)(g_yslot + (size_t)s1 * H_DIM);
    const float4* x1 = (const float4*)(g_x1 + (size_t)t * H_DIM);
    float4* o = (float4*)(out + (size_t)t * H_DIM);
    int i = threadIdx.x;
    float4 a = x1[i], b = y0[i], c = y1[i];
    float4 r;
    r.x = a.x + g0 * b.x + g1 * c.x;
    r.y = a.y + g0 * b.y + g1 * c.y;
    r.z = a.z + g0 * b.z + g1 * c.z;
    r.w = a.w + g0 * b.w + g1 * c.w;
    o[i] = r;
}

// ---------------- launch ----------------
extern "C" void kernel_launch(void* const* d_in, const int* in_sizes, int n_in,
                              void* d_out, int out_size) {
    (void)in_sizes; (void)n_in; (void)out_size;
    const float* x          = (const float*)d_in[0];
    const float* ln1_w      = (const float*)d_in[1];
    const float* ln1_b      = (const float*)d_in[2];
    const float* in_proj_w  = (const float*)d_in[3];
    const float* in_proj_b  = (const float*)d_in[4];
    const float* out_proj_w = (const float*)d_in[5];
    const float* out_proj_b = (const float*)d_in[6];
    const float* ln2_w      = (const float*)d_in[7];
    const float* ln2_b      = (const float*)d_in[8];
    const float* router_w   = (const float*)d_in[9];
    const float* w1         = (const float*)d_in[10];
    const float* w2         = (const float*)d_in[11];
    float* out = (float*)d_out;

    static int attr_set = 0;
    if (!attr_set) {
        cudaFuncSetAttribute(gemm_nt_tc<0>, cudaFuncAttributeMaxDynamicSharedMemorySize, GEMM_SMEM);
        cudaFuncSetAttribute(gemm_nt_tc<1>, cudaFuncAttributeMaxDynamicSharedMemorySize, GEMM_SMEM);
        cudaFuncSetAttribute(moe_gemm_tc<1>, cudaFuncAttributeMaxDynamicSharedMemorySize, MOE_SMEM);
        cudaFuncSetAttribute(moe_gemm_tc<2>, cudaFuncAttributeMaxDynamicSharedMemorySize, MOE_SMEM);
        attr_set = 1;
    }

    // weight tf32-rounding copies (in/out proj only)
    {
        float* ipw_d = nullptr;
        float* opw_d = nullptr;
        cudaGetSymbolAddress((void**)&ipw_d, g_ipw);
        cudaGetSymbolAddress((void**)&opw_d, g_opw);
        int n4a = H3 * H_DIM / 4;
        int n4b = H_DIM * H_DIM / 4;
        cvt_w_kernel<<<(n4a + 255) / 256, 256>>>((const float4*)in_proj_w, (float4*)ipw_d, n4a);
        cvt_w_kernel<<<(n4b + 255) / 256, 256>>>((const float4*)out_proj_w, (float4*)opw_d, n4b);
    }

    ln_kernel<0><<<S_LEN, 256>>>(x, ln1_w, ln1_b);
    gemm_nt_tc<0><<<dim3(H3 / 128, S_LEN / 128), 256, GEMM_SMEM>>>(in_proj_b, nullptr);
    attn_tc<<<dim3(S_LEN / 64, NH), 128>>>();
    gemm_nt_tc<1><<<dim3(H_DIM / 128, S_LEN / 128), 256, GEMM_SMEM>>>(out_proj_b, x);
    ln_kernel<1><<<S_LEN, 256>>>(nullptr, ln2_w, ln2_b);
    zero_kernel<<<1, 32>>>();
    router_kernel<<<S_LEN, 128>>>(router_w);
    scan_kernel<<<1, 32>>>();
    fill_kernel<<<S_LEN / 256, 256>>>();
    moe_gemm_tc<1><<<dim3(FF / 128, S_LEN / 128, NE), 256, MOE_SMEM>>>(w1);
    moe_gemm_tc<2><<<dim3(H_DIM / 128, S_LEN / 128, NE), 256, MOE_SMEM>>>(w2);
    combine_kernel<<<S_LEN, 256>>>(out);
}